// round 1
// baseline (speedup 1.0000x reference)
#include <cuda_runtime.h>
#include <math.h>

// ---------------- problem constants ----------------
constexpr int SEQ  = 2048;
constexpr int HID  = 2048;
constexpr int NHEAD = 32;
constexpr int NKVH  = 8;
constexpr int HDIM  = 64;
constexpr int RLEN  = 1024;      // retrieval tokens (prepended)
constexpr float SCALE = 0.125f;  // HD^-0.5

// ---------------- scratch (no allocs allowed) ----------------
__device__ float g_q [SEQ * NHEAD * HDIM];   // 16 MB
__device__ float g_k [SEQ * NKVH  * HDIM];   // 4 MB
__device__ float g_v [SEQ * NKVH  * HDIM];   // 4 MB
__device__ float g_ao[SEQ * NHEAD * HDIM];   // 16 MB

// ---------------- fp32 tiled GEMM: C(MxN) = A(MxK) @ B(KxN), all row-major ----
// BM=128, BN=128, BK=16, 256 threads, 8x8 microtile per thread.
__global__ __launch_bounds__(256)
void sgemm_kernel(const float* __restrict__ A, const float* __restrict__ B,
                  float* __restrict__ C, int M, int N, int K)
{
    __shared__ float As[16][132];   // [k][m], padded
    __shared__ float Bs[16][132];   // [k][n], padded

    const int bm = blockIdx.y * 128;
    const int bn = blockIdx.x * 128;
    const int tid = threadIdx.x;
    const int tx = tid & 15;        // 0..15 -> 8 cols each
    const int ty = tid >> 4;        // 0..15 -> 8 rows each

    // A load mapping: 128 rows x 4 float4(k) -> 512 float4, 2 per thread
    const int aRow = tid >> 2;          // 0..63
    const int aK4  = (tid & 3) * 4;     // 0,4,8,12
    // B load mapping: 16 k-rows x 32 float4(n) -> 512 float4, 2 per thread
    const int bK  = tid >> 4;           // 0..15
    const int bN4 = (tid & 15) * 4;     // 0..60

    float acc[8][8];
#pragma unroll
    for (int i = 0; i < 8; i++)
#pragma unroll
        for (int j = 0; j < 8; j++) acc[i][j] = 0.f;

    for (int k0 = 0; k0 < K; k0 += 16) {
#pragma unroll
        for (int i = 0; i < 2; i++) {
            int r = aRow + 64 * i;
            float4 va = *(const float4*)&A[(size_t)(bm + r) * K + k0 + aK4];
            As[aK4 + 0][r] = va.x;
            As[aK4 + 1][r] = va.y;
            As[aK4 + 2][r] = va.z;
            As[aK4 + 3][r] = va.w;
        }
#pragma unroll
        for (int i = 0; i < 2; i++) {
            int c = bN4 + 64 * i;
            *(float4*)&Bs[bK][c] = *(const float4*)&B[(size_t)(k0 + bK) * N + bn + c];
        }
        __syncthreads();

#pragma unroll
        for (int kk = 0; kk < 16; kk++) {
            float4 a0 = *(const float4*)&As[kk][ty * 8];
            float4 a1 = *(const float4*)&As[kk][ty * 8 + 4];
            float4 b0 = *(const float4*)&Bs[kk][tx * 8];
            float4 b1 = *(const float4*)&Bs[kk][tx * 8 + 4];
            float a[8] = {a0.x, a0.y, a0.z, a0.w, a1.x, a1.y, a1.z, a1.w};
            float b[8] = {b0.x, b0.y, b0.z, b0.w, b1.x, b1.y, b1.z, b1.w};
#pragma unroll
            for (int i = 0; i < 8; i++)
#pragma unroll
                for (int j = 0; j < 8; j++) acc[i][j] += a[i] * b[j];
        }
        __syncthreads();
    }

#pragma unroll
    for (int i = 0; i < 8; i++) {
        float4 o0 = make_float4(acc[i][0], acc[i][1], acc[i][2], acc[i][3]);
        float4 o1 = make_float4(acc[i][4], acc[i][5], acc[i][6], acc[i][7]);
        size_t row = (size_t)(bm + ty * 8 + i) * N + bn + tx * 8;
        *(float4*)&C[row]     = o0;
        *(float4*)&C[row + 4] = o1;
    }
}

// ---------------- RoPE (in-place on q and k) ----------------
__global__ void rope_kernel(float* __restrict__ q, float* __restrict__ k,
                            const float* __restrict__ cosb, const float* __restrict__ sinb)
{
    const int QT = SEQ * NHEAD * (HDIM / 2);
    const int KT = SEQ * NKVH  * (HDIM / 2);
    int idx = blockIdx.x * blockDim.x + threadIdx.x;
    if (idx < QT) {
        int i = idx & 31;
        int rem = idx >> 5;
        int h = rem % NHEAD;
        int srow = rem / NHEAD;
        float* base = q + (size_t)srow * (NHEAD * HDIM) + h * HDIM;
        float c0 = cosb[srow * HDIM + i],      c1 = cosb[srow * HDIM + 32 + i];
        float s0 = sinb[srow * HDIM + i],      s1 = sinb[srow * HDIM + 32 + i];
        float x0 = base[i], x1 = base[i + 32];
        base[i]      = x0 * c0 - x1 * s0;
        base[i + 32] = x1 * c1 + x0 * s1;
    } else if (idx < QT + KT) {
        int id2 = idx - QT;
        int i = id2 & 31;
        int rem = id2 >> 5;
        int h = rem % NKVH;
        int srow = rem / NKVH;
        float* base = k + (size_t)srow * (NKVH * HDIM) + h * HDIM;
        float c0 = cosb[srow * HDIM + i],      c1 = cosb[srow * HDIM + 32 + i];
        float s0 = sinb[srow * HDIM + i],      s1 = sinb[srow * HDIM + 32 + i];
        float x0 = base[i], x1 = base[i + 32];
        base[i]      = x0 * c0 - x1 * s0;
        base[i + 32] = x1 * c1 + x0 * s1;
    }
}

// ---------------- flash attention exploiting the block mask ----------------
// Query tile t covers s in [64t, 64t+64); all those queries share chunk id t.
//   - if t >= 1: attend retrieval block rb = min(t,16)-1 (64 tokens, unmasked)
//   - causal over new tokens n in [1, s]  -> new tiles j = 0..t (j==t diagonal)
// grid = (32 q-tiles, 32 heads), 256 threads, dynamic smem 4*64*65 floats.
__global__ __launch_bounds__(256)
void attn_kernel(const float* __restrict__ q, const float* __restrict__ kbuf,
                 const float* __restrict__ vbuf, const float* __restrict__ rk,
                 const float* __restrict__ rv, float* __restrict__ out)
{
    extern __shared__ float sm[];
    float* Qs = sm;                 // [64][65]
    float* Ks = sm + 64 * 65;       // [64][65]
    float* Vs = sm + 2 * 64 * 65;   // [64][65]
    float* Ps = sm + 3 * 64 * 65;   // [64][65]

    const int t  = (int)gridDim.x - 1 - (int)blockIdx.x;  // big tiles first
    const int h  = blockIdx.y;
    const int hk = h >> 2;                                // GQA: 4 q-heads per kv-head
    const int tid = threadIdx.x;
    const int ty = tid >> 4, tx = tid & 15;
    const int r0 = ty * 4, c0 = tx * 4;

    // load Q tile (pre-scaled)
    for (int i = tid; i < 64 * 64; i += 256) {
        int r = i >> 6, d = i & 63;
        Qs[r * 65 + d] = q[(size_t)(t * 64 + r) * (NHEAD * HDIM) + h * HDIM + d] * SCALE;
    }

    float m_i[4], l_i[4], O[4][4];
#pragma unroll
    for (int i = 0; i < 4; i++) {
        m_i[i] = -1e30f; l_i[i] = 0.f;
#pragma unroll
        for (int j = 0; j < 4; j++) O[i][j] = 0.f;
    }

    const int hasret = (t >= 1) ? 1 : 0;
    const int ntiles = (t + 1) + hasret;

    for (int it = 0; it < ntiles; it++) {
        const bool isret = hasret && (it == 0);
        const int jt = it - hasret;     // new tile index when !isret
        __syncthreads();                // protect prev-iter Ks/Vs/Ps reads (and Qs on iter 0)

        if (isret) {
            const int rb = ((t < 16) ? t : 16) - 1;
            const float* kb = rk + (size_t)(hk * RLEN + rb * 64) * HDIM;
            const float* vb = rv + (size_t)(hk * RLEN + rb * 64) * HDIM;
            for (int i = tid; i < 4096; i += 256) {
                int r = i >> 6, d = i & 63;
                Ks[r * 65 + d] = kb[r * HDIM + d];
                Vs[r * 65 + d] = vb[r * HDIM + d];
            }
        } else {
            const int base = jt * 64;
            for (int i = tid; i < 4096; i += 256) {
                int r = i >> 6, d = i & 63;
                size_t src = (size_t)(base + r) * (NKVH * HDIM) + hk * HDIM + d;
                Ks[r * 65 + d] = kbuf[src];
                Vs[r * 65 + d] = vbuf[src];
            }
        }
        __syncthreads();

        // S = Q K^T  (4x4 per thread)
        float sv[4][4];
#pragma unroll
        for (int i = 0; i < 4; i++)
#pragma unroll
            for (int j = 0; j < 4; j++) sv[i][j] = 0.f;

        for (int d = 0; d < 64; d++) {
            float a[4], b[4];
#pragma unroll
            for (int i = 0; i < 4; i++) a[i] = Qs[(r0 + i) * 65 + d];
#pragma unroll
            for (int j = 0; j < 4; j++) b[j] = Ks[(c0 + j) * 65 + d];
#pragma unroll
            for (int i = 0; i < 4; i++)
#pragma unroll
                for (int j = 0; j < 4; j++) sv[i][j] += a[i] * b[j];
        }

        // mask (new tiles only; retrieval block is fully valid)
        if (!isret) {
#pragma unroll
            for (int i = 0; i < 4; i++) {
                int s = t * 64 + r0 + i;
#pragma unroll
                for (int j = 0; j < 4; j++) {
                    int n = jt * 64 + c0 + j;
                    if (n < 1 || n > s) sv[i][j] = -1e30f;
                }
            }
        }

        // online softmax: rows r0..r0+3 owned by the 16 threads sharing ty
#pragma unroll
        for (int i = 0; i < 4; i++) {
            float lm = fmaxf(fmaxf(sv[i][0], sv[i][1]), fmaxf(sv[i][2], sv[i][3]));
#pragma unroll
            for (int off = 8; off > 0; off >>= 1)
                lm = fmaxf(lm, __shfl_xor_sync(0xffffffffu, lm, off));
            float nm = fmaxf(m_i[i], lm);
            float rs = 0.f;
#pragma unroll
            for (int j = 0; j < 4; j++) {
                sv[i][j] = __expf(sv[i][j] - nm);
                rs += sv[i][j];
            }
#pragma unroll
            for (int off = 8; off > 0; off >>= 1)
                rs += __shfl_xor_sync(0xffffffffu, rs, off);
            float f = __expf(m_i[i] - nm);
            m_i[i] = nm;
            l_i[i] = l_i[i] * f + rs;
#pragma unroll
            for (int j = 0; j < 4; j++) O[i][j] *= f;
#pragma unroll
            for (int j = 0; j < 4; j++) Ps[(r0 + i) * 65 + c0 + j] = sv[i][j];
        }
        __syncthreads();

        // O += P @ V
        for (int kk = 0; kk < 64; kk++) {
            float a[4], b[4];
#pragma unroll
            for (int i = 0; i < 4; i++) a[i] = Ps[(r0 + i) * 65 + kk];
#pragma unroll
            for (int j = 0; j < 4; j++) b[j] = Vs[kk * 65 + c0 + j];
#pragma unroll
            for (int i = 0; i < 4; i++)
#pragma unroll
                for (int j = 0; j < 4; j++) O[i][j] += a[i] * b[j];
        }
    }

    // epilogue: rows that never saw a valid key (only s==0) -> 0
#pragma unroll
    for (int i = 0; i < 4; i++) {
        float inv = (m_i[i] > -1e29f) ? (1.f / l_i[i]) : 0.f;
#pragma unroll
        for (int j = 0; j < 4; j++)
            out[(size_t)(t * 64 + r0 + i) * (NHEAD * HDIM) + h * HDIM + c0 + j] = O[i][j] * inv;
    }
}

// ---------------- launch ----------------
extern "C" void kernel_launch(void* const* d_in, const int* in_sizes, int n_in,
                              void* d_out, int out_size)
{
    const float* hidden = (const float*)d_in[0];
    const float* cosb   = (const float*)d_in[1];
    const float* sinb   = (const float*)d_in[2];
    const float* rk     = (const float*)d_in[3];
    const float* rv     = (const float*)d_in[4];
    const float* Wq     = (const float*)d_in[5];
    const float* Wk     = (const float*)d_in[6];
    const float* Wv     = (const float*)d_in[7];
    const float* Wo     = (const float*)d_in[8];
    float* out = (float*)d_out;

    float *q, *k, *v, *ao;
    cudaGetSymbolAddress((void**)&q,  g_q);
    cudaGetSymbolAddress((void**)&k,  g_k);
    cudaGetSymbolAddress((void**)&v,  g_v);
    cudaGetSymbolAddress((void**)&ao, g_ao);

    // QKV projections
    sgemm_kernel<<<dim3((NHEAD * HDIM) / 128, SEQ / 128), 256>>>(hidden, Wq, q, SEQ, NHEAD * HDIM, HID);
    sgemm_kernel<<<dim3((NKVH  * HDIM) / 128, SEQ / 128), 256>>>(hidden, Wk, k, SEQ, NKVH * HDIM, HID);
    sgemm_kernel<<<dim3((NKVH  * HDIM) / 128, SEQ / 128), 256>>>(hidden, Wv, v, SEQ, NKVH * HDIM, HID);

    // RoPE on q and k
    {
        int total = SEQ * (NHEAD + NKVH) * (HDIM / 2);
        rope_kernel<<<(total + 255) / 256, 256>>>(q, k, cosb, sinb);
    }

    // masked flash attention
    const int attn_smem = 4 * 64 * 65 * (int)sizeof(float);  // 66560 B
    cudaFuncSetAttribute(attn_kernel, cudaFuncAttributeMaxDynamicSharedMemorySize, attn_smem);
    attn_kernel<<<dim3(SEQ / 64, NHEAD), 256, attn_smem>>>(q, k, v, rk, rv, ao);

    // output projection
    sgemm_kernel<<<dim3(HID / 128, SEQ / 128), 256>>>(ao, Wo, out, SEQ, HID, HID);
}

// round 2
// speedup vs baseline: 1.9447x; 1.9447x over previous
#include <cuda_runtime.h>
#include <math.h>

// ---------------- problem constants ----------------
constexpr int SEQ  = 2048;
constexpr int HID  = 2048;
constexpr int NHEAD = 32;
constexpr int NKVH  = 8;
constexpr int HDIM  = 64;
constexpr int RLEN  = 1024;
constexpr float SCALE = 0.125f;

// ---------------- scratch ----------------
__device__ float g_q [SEQ * NHEAD * HDIM];
__device__ float g_k [SEQ * NKVH  * HDIM];
__device__ float g_v [SEQ * NKVH  * HDIM];
__device__ float g_ao[SEQ * NHEAD * HDIM];

// ---------------- tf32 helpers ----------------
__device__ __forceinline__ unsigned f2tf(float x) {
    unsigned r;
    asm("cvt.rna.tf32.f32 %0, %1;" : "=r"(r) : "f"(x));
    return r;
}
// D(16x8) += A(16x8,row) * B(8x8,col)  tf32
__device__ __forceinline__ void mma8(float* c, const unsigned* a, const unsigned* b) {
    asm volatile(
        "mma.sync.aligned.m16n8k8.row.col.f32.tf32.tf32.f32 "
        "{%0,%1,%2,%3},{%4,%5,%6,%7},{%8,%9},{%0,%1,%2,%3};"
        : "+f"(c[0]), "+f"(c[1]), "+f"(c[2]), "+f"(c[3])
        : "r"(a[0]), "r"(a[1]), "r"(a[2]), "r"(a[3]), "r"(b[0]), "r"(b[1]));
}

// ---------------- tf32 tensor-core GEMM: C = A(MxK) @ B(KxN), row-major ------
// BM=128 BN=128 BK=16, 256 threads = 8 warps (4m x 2n); warp = 32x64.
__global__ __launch_bounds__(256)
void tf32_gemm(const float* __restrict__ A, const float* __restrict__ B,
               float* __restrict__ C, int M, int N, int K)
{
    __shared__ unsigned As[16][132];   // [k][m], stride%32==4: conflict-free A frags
    __shared__ unsigned Bs[16][136];   // [k][n], stride%32==8: conflict-free B frags

    const int bm = blockIdx.y * 128;
    const int bn = blockIdx.x * 128;
    const int tid  = threadIdx.x;
    const int warp = tid >> 5;
    const int lane = tid & 31;
    const int gid  = lane >> 2;
    const int tig  = lane & 3;
    const int wm = warp >> 1;            // 0..3
    const int wn = warp & 1;             // 0..1
    const int m_base = wm * 32;
    const int n_base = wn * 64;

    const int aRow = tid >> 2;           // 0..63
    const int aK4  = (tid & 3) * 4;      // 0,4,8,12
    const int bK   = tid >> 4;           // 0..15
    const int bN4  = (tid & 15) * 4;     // 0..60

    float acc[2][8][4];
#pragma unroll
    for (int mt = 0; mt < 2; mt++)
#pragma unroll
        for (int nt = 0; nt < 8; nt++)
#pragma unroll
            for (int j = 0; j < 4; j++) acc[mt][nt][j] = 0.f;

    for (int k0 = 0; k0 < K; k0 += 16) {
#pragma unroll
        for (int i = 0; i < 2; i++) {
            int r = aRow + 64 * i;
            float4 va = *(const float4*)&A[(size_t)(bm + r) * K + k0 + aK4];
            As[aK4 + 0][r] = f2tf(va.x);
            As[aK4 + 1][r] = f2tf(va.y);
            As[aK4 + 2][r] = f2tf(va.z);
            As[aK4 + 3][r] = f2tf(va.w);
        }
#pragma unroll
        for (int i = 0; i < 2; i++) {
            int c = bN4 + 64 * i;
            float4 vb = *(const float4*)&B[(size_t)(k0 + bK) * N + bn + c];
            Bs[bK][c + 0] = f2tf(vb.x);
            Bs[bK][c + 1] = f2tf(vb.y);
            Bs[bK][c + 2] = f2tf(vb.z);
            Bs[bK][c + 3] = f2tf(vb.w);
        }
        __syncthreads();

#pragma unroll
        for (int ks = 0; ks < 2; ks++) {
            const int kb = ks * 8;
            unsigned a[2][4];
#pragma unroll
            for (int mt = 0; mt < 2; mt++) {
                a[mt][0] = As[kb + tig    ][m_base + mt * 16 + gid];
                a[mt][1] = As[kb + tig    ][m_base + mt * 16 + gid + 8];
                a[mt][2] = As[kb + tig + 4][m_base + mt * 16 + gid];
                a[mt][3] = As[kb + tig + 4][m_base + mt * 16 + gid + 8];
            }
#pragma unroll
            for (int nt = 0; nt < 8; nt++) {
                unsigned b[2];
                b[0] = Bs[kb + tig    ][n_base + nt * 8 + gid];
                b[1] = Bs[kb + tig + 4][n_base + nt * 8 + gid];
                mma8(acc[0][nt], a[0], b);
                mma8(acc[1][nt], a[1], b);
            }
        }
        __syncthreads();
    }

#pragma unroll
    for (int mt = 0; mt < 2; mt++)
#pragma unroll
        for (int nt = 0; nt < 8; nt++) {
            int row = bm + m_base + mt * 16 + gid;
            int col = bn + n_base + nt * 8 + 2 * tig;
            *(float2*)&C[(size_t)row * N + col]       = make_float2(acc[mt][nt][0], acc[mt][nt][1]);
            *(float2*)&C[(size_t)(row + 8) * N + col] = make_float2(acc[mt][nt][2], acc[mt][nt][3]);
        }
}

// ---------------- RoPE (unchanged) ----------------
__global__ void rope_kernel(float* __restrict__ q, float* __restrict__ k,
                            const float* __restrict__ cosb, const float* __restrict__ sinb)
{
    const int QT = SEQ * NHEAD * (HDIM / 2);
    const int KT = SEQ * NKVH  * (HDIM / 2);
    int idx = blockIdx.x * blockDim.x + threadIdx.x;
    if (idx < QT) {
        int i = idx & 31;
        int rem = idx >> 5;
        int h = rem % NHEAD;
        int srow = rem / NHEAD;
        float* base = q + (size_t)srow * (NHEAD * HDIM) + h * HDIM;
        float c0 = cosb[srow * HDIM + i],      c1 = cosb[srow * HDIM + 32 + i];
        float s0 = sinb[srow * HDIM + i],      s1 = sinb[srow * HDIM + 32 + i];
        float x0 = base[i], x1 = base[i + 32];
        base[i]      = x0 * c0 - x1 * s0;
        base[i + 32] = x1 * c1 + x0 * s1;
    } else if (idx < QT + KT) {
        int id2 = idx - QT;
        int i = id2 & 31;
        int rem = id2 >> 5;
        int h = rem % NKVH;
        int srow = rem / NKVH;
        float* base = k + (size_t)srow * (NKVH * HDIM) + h * HDIM;
        float c0 = cosb[srow * HDIM + i],      c1 = cosb[srow * HDIM + 32 + i];
        float s0 = sinb[srow * HDIM + i],      s1 = sinb[srow * HDIM + 32 + i];
        float x0 = base[i], x1 = base[i + 32];
        base[i]      = x0 * c0 - x1 * s0;
        base[i + 32] = x1 * c1 + x0 * s1;
    }
}

// ---------------- tf32 tensor-core flash attention (mask-aware) ----------------
// 128 threads = 4 warps; warp w owns query rows [16w,16w+16).
// smem (tf32 bits): Qs[64][68], Ks[64][72] (d-major), Vs[64][72], Ps[64][68]
constexpr int QS_STR = 68;   // %32==4: A-frag conflict-free
constexpr int KS_STR = 72;   // %32==8: B-frag conflict-free
constexpr int SM_QS = 0;
constexpr int SM_KS = 64 * QS_STR;
constexpr int SM_VS = SM_KS + 64 * KS_STR;
constexpr int SM_PS = SM_VS + 64 * KS_STR;
constexpr int ATTN_SMEM_WORDS = SM_PS + 64 * QS_STR;

__global__ __launch_bounds__(128)
void attn_tc(const float* __restrict__ q, const float* __restrict__ kbuf,
             const float* __restrict__ vbuf, const float* __restrict__ rk,
             const float* __restrict__ rv, float* __restrict__ out)
{
    extern __shared__ unsigned sm[];
    unsigned* Qs = sm + SM_QS;
    unsigned* Ks = sm + SM_KS;
    unsigned* Vs = sm + SM_VS;
    unsigned* Ps = sm + SM_PS;

    const int t  = (int)gridDim.x - 1 - (int)blockIdx.x;
    const int h  = blockIdx.y;
    const int hk = h >> 2;
    const int tid  = threadIdx.x;
    const int warp = tid >> 5;
    const int lane = tid & 31;
    const int gid  = lane >> 2;
    const int tig  = lane & 3;
    const int q0 = warp * 16;

    // load Q tile (scaled, tf32)
    for (int i = tid; i < 1024; i += 128) {
        int r = i >> 4, d0 = (i & 15) * 4;
        float4 v = *(const float4*)&q[(size_t)(t * 64 + r) * (NHEAD * HDIM) + h * HDIM + d0];
        Qs[r * QS_STR + d0 + 0] = f2tf(v.x * SCALE);
        Qs[r * QS_STR + d0 + 1] = f2tf(v.y * SCALE);
        Qs[r * QS_STR + d0 + 2] = f2tf(v.z * SCALE);
        Qs[r * QS_STR + d0 + 3] = f2tf(v.w * SCALE);
    }

    float m_lo = -1e30f, m_hi = -1e30f, l_lo = 0.f, l_hi = 0.f;
    float O[8][4];
#pragma unroll
    for (int nt = 0; nt < 8; nt++)
#pragma unroll
        for (int j = 0; j < 4; j++) O[nt][j] = 0.f;

    const int hasret = (t >= 1) ? 1 : 0;
    const int ntiles = (t + 1) + hasret;

    for (int it = 0; it < ntiles; it++) {
        const bool isret = hasret && (it == 0);
        const int jt = it - hasret;
        __syncthreads();  // prior-iter K/V reads complete

        if (isret) {
            const int rb = ((t < 16) ? t : 16) - 1;
            const float* kb = rk + (size_t)(hk * RLEN + rb * 64) * HDIM;
            const float* vb = rv + (size_t)(hk * RLEN + rb * 64) * HDIM;
            for (int i = tid; i < 1024; i += 128) {
                int r = i >> 4, d0 = (i & 15) * 4;
                float4 kv = *(const float4*)&kb[r * HDIM + d0];
                Ks[(d0 + 0) * KS_STR + r] = f2tf(kv.x);
                Ks[(d0 + 1) * KS_STR + r] = f2tf(kv.y);
                Ks[(d0 + 2) * KS_STR + r] = f2tf(kv.z);
                Ks[(d0 + 3) * KS_STR + r] = f2tf(kv.w);
                float4 vv = *(const float4*)&vb[r * HDIM + d0];
                Vs[r * KS_STR + d0 + 0] = f2tf(vv.x);
                Vs[r * KS_STR + d0 + 1] = f2tf(vv.y);
                Vs[r * KS_STR + d0 + 2] = f2tf(vv.z);
                Vs[r * KS_STR + d0 + 3] = f2tf(vv.w);
            }
        } else {
            const int base = jt * 64;
            for (int i = tid; i < 1024; i += 128) {
                int r = i >> 4, d0 = (i & 15) * 4;
                size_t src = (size_t)(base + r) * (NKVH * HDIM) + hk * HDIM + d0;
                float4 kv = *(const float4*)&kbuf[src];
                Ks[(d0 + 0) * KS_STR + r] = f2tf(kv.x);
                Ks[(d0 + 1) * KS_STR + r] = f2tf(kv.y);
                Ks[(d0 + 2) * KS_STR + r] = f2tf(kv.z);
                Ks[(d0 + 3) * KS_STR + r] = f2tf(kv.w);
                float4 vv = *(const float4*)&vbuf[src];
                Vs[r * KS_STR + d0 + 0] = f2tf(vv.x);
                Vs[r * KS_STR + d0 + 1] = f2tf(vv.y);
                Vs[r * KS_STR + d0 + 2] = f2tf(vv.z);
                Vs[r * KS_STR + d0 + 3] = f2tf(vv.w);
            }
        }
        __syncthreads();

        // S = Q K^T  — 1 m-tile x 8 n-tiles x 8 k-steps per warp
        float sacc[8][4];
#pragma unroll
        for (int nt = 0; nt < 8; nt++)
#pragma unroll
            for (int j = 0; j < 4; j++) sacc[nt][j] = 0.f;

#pragma unroll
        for (int kt = 0; kt < 8; kt++) {
            unsigned a[4];
            a[0] = Qs[(q0 + gid    ) * QS_STR + kt * 8 + tig];
            a[1] = Qs[(q0 + gid + 8) * QS_STR + kt * 8 + tig];
            a[2] = Qs[(q0 + gid    ) * QS_STR + kt * 8 + tig + 4];
            a[3] = Qs[(q0 + gid + 8) * QS_STR + kt * 8 + tig + 4];
#pragma unroll
            for (int nt = 0; nt < 8; nt++) {
                unsigned b[2];
                b[0] = Ks[(kt * 8 + tig    ) * KS_STR + nt * 8 + gid];
                b[1] = Ks[(kt * 8 + tig + 4) * KS_STR + nt * 8 + gid];
                mma8(sacc[nt], a, b);
            }
        }

        // mask (new-token tiles only)
        if (!isret) {
            const int s_lo = t * 64 + q0 + gid;
            const int s_hi = s_lo + 8;
#pragma unroll
            for (int nt = 0; nt < 8; nt++) {
#pragma unroll
                for (int j = 0; j < 2; j++) {
                    int n = jt * 64 + nt * 8 + 2 * tig + j;
                    bool inval = (n < 1);
                    if (inval || n > s_lo) sacc[nt][j]     = -1e30f;
                    if (inval || n > s_hi) sacc[nt][j + 2] = -1e30f;
                }
            }
        }

        // online softmax (rows lo/hi; quad = lanes sharing gid)
        float lm_lo = -1e30f, lm_hi = -1e30f;
#pragma unroll
        for (int nt = 0; nt < 8; nt++) {
            lm_lo = fmaxf(lm_lo, fmaxf(sacc[nt][0], sacc[nt][1]));
            lm_hi = fmaxf(lm_hi, fmaxf(sacc[nt][2], sacc[nt][3]));
        }
        lm_lo = fmaxf(lm_lo, __shfl_xor_sync(0xffffffffu, lm_lo, 1));
        lm_lo = fmaxf(lm_lo, __shfl_xor_sync(0xffffffffu, lm_lo, 2));
        lm_hi = fmaxf(lm_hi, __shfl_xor_sync(0xffffffffu, lm_hi, 1));
        lm_hi = fmaxf(lm_hi, __shfl_xor_sync(0xffffffffu, lm_hi, 2));
        const float mn_lo = fmaxf(m_lo, lm_lo);
        const float mn_hi = fmaxf(m_hi, lm_hi);

        float sum_lo = 0.f, sum_hi = 0.f;
#pragma unroll
        for (int nt = 0; nt < 8; nt++) {
#pragma unroll
            for (int j = 0; j < 2; j++) {
                float p0 = __expf(sacc[nt][j]     - mn_lo);
                float p1 = __expf(sacc[nt][j + 2] - mn_hi);
                sum_lo += p0;
                sum_hi += p1;
                Ps[(q0 + gid    ) * QS_STR + nt * 8 + 2 * tig + j] = f2tf(p0);
                Ps[(q0 + gid + 8) * QS_STR + nt * 8 + 2 * tig + j] = f2tf(p1);
            }
        }
        sum_lo += __shfl_xor_sync(0xffffffffu, sum_lo, 1);
        sum_lo += __shfl_xor_sync(0xffffffffu, sum_lo, 2);
        sum_hi += __shfl_xor_sync(0xffffffffu, sum_hi, 1);
        sum_hi += __shfl_xor_sync(0xffffffffu, sum_hi, 2);

        const float f_lo = __expf(m_lo - mn_lo);
        const float f_hi = __expf(m_hi - mn_hi);
        m_lo = mn_lo; m_hi = mn_hi;
        l_lo = l_lo * f_lo + sum_lo;
        l_hi = l_hi * f_hi + sum_hi;
#pragma unroll
        for (int nt = 0; nt < 8; nt++) {
            O[nt][0] *= f_lo; O[nt][1] *= f_lo;
            O[nt][2] *= f_hi; O[nt][3] *= f_hi;
        }
        __syncwarp();  // Ps rows are warp-private; warp-level visibility is enough

        // O += P @ V
#pragma unroll
        for (int kt = 0; kt < 8; kt++) {
            unsigned a[4];
            a[0] = Ps[(q0 + gid    ) * QS_STR + kt * 8 + tig];
            a[1] = Ps[(q0 + gid + 8) * QS_STR + kt * 8 + tig];
            a[2] = Ps[(q0 + gid    ) * QS_STR + kt * 8 + tig + 4];
            a[3] = Ps[(q0 + gid + 8) * QS_STR + kt * 8 + tig + 4];
#pragma unroll
            for (int nt = 0; nt < 8; nt++) {
                unsigned b[2];
                b[0] = Vs[(kt * 8 + tig    ) * KS_STR + nt * 8 + gid];
                b[1] = Vs[(kt * 8 + tig + 4) * KS_STR + nt * 8 + gid];
                mma8(O[nt], a, b);
            }
        }
    }

    // epilogue
    const float inv_lo = (m_lo > -1e29f) ? (1.f / l_lo) : 0.f;
    const float inv_hi = (m_hi > -1e29f) ? (1.f / l_hi) : 0.f;
#pragma unroll
    for (int nt = 0; nt < 8; nt++) {
        int col = nt * 8 + 2 * tig;
        size_t r_lo = (size_t)(t * 64 + q0 + gid)     * (NHEAD * HDIM) + h * HDIM + col;
        size_t r_hi = (size_t)(t * 64 + q0 + gid + 8) * (NHEAD * HDIM) + h * HDIM + col;
        *(float2*)&out[r_lo] = make_float2(O[nt][0] * inv_lo, O[nt][1] * inv_lo);
        *(float2*)&out[r_hi] = make_float2(O[nt][2] * inv_hi, O[nt][3] * inv_hi);
    }
}

// ---------------- launch ----------------
extern "C" void kernel_launch(void* const* d_in, const int* in_sizes, int n_in,
                              void* d_out, int out_size)
{
    const float* hidden = (const float*)d_in[0];
    const float* cosb   = (const float*)d_in[1];
    const float* sinb   = (const float*)d_in[2];
    const float* rk     = (const float*)d_in[3];
    const float* rv     = (const float*)d_in[4];
    const float* Wq     = (const float*)d_in[5];
    const float* Wk     = (const float*)d_in[6];
    const float* Wv     = (const float*)d_in[7];
    const float* Wo     = (const float*)d_in[8];
    float* out = (float*)d_out;

    float *q, *k, *v, *ao;
    cudaGetSymbolAddress((void**)&q,  g_q);
    cudaGetSymbolAddress((void**)&k,  g_k);
    cudaGetSymbolAddress((void**)&v,  g_v);
    cudaGetSymbolAddress((void**)&ao, g_ao);

    tf32_gemm<<<dim3((NHEAD * HDIM) / 128, SEQ / 128), 256>>>(hidden, Wq, q, SEQ, NHEAD * HDIM, HID);
    tf32_gemm<<<dim3((NKVH  * HDIM) / 128, SEQ / 128), 256>>>(hidden, Wk, k, SEQ, NKVH * HDIM, HID);
    tf32_gemm<<<dim3((NKVH  * HDIM) / 128, SEQ / 128), 256>>>(hidden, Wv, v, SEQ, NKVH * HDIM, HID);

    {
        int total = SEQ * (NHEAD + NKVH) * (HDIM / 2);
        rope_kernel<<<(total + 255) / 256, 256>>>(q, k, cosb, sinb);
    }

    const int attn_smem = ATTN_SMEM_WORDS * (int)sizeof(unsigned);  // 71680 B
    cudaFuncSetAttribute(attn_tc, cudaFuncAttributeMaxDynamicSharedMemorySize, attn_smem);
    attn_tc<<<dim3(SEQ / 64, NHEAD), 128, attn_smem>>>(q, k, v, rk, rv, ao);

    tf32_gemm<<<dim3(HID / 128, SEQ / 128), 256>>>(ao, Wo, out, SEQ, HID, HID);
}

// round 3
// speedup vs baseline: 3.0242x; 1.5551x over previous
#include <cuda_runtime.h>
#include <math.h>

// ---------------- problem constants ----------------
constexpr int SEQ  = 2048;
constexpr int HID  = 2048;
constexpr int NHEAD = 32;
constexpr int NKVH  = 8;
constexpr int HDIM  = 64;
constexpr int RLEN  = 1024;
constexpr int KVTOT = RLEN + SEQ;   // 3072
constexpr float SCALE = 0.125f;

// ---------------- scratch (device globals; no allocs) ----------------
__device__ float    g_q [SEQ * NHEAD * HDIM];   // GEMM out -> rope converts in place to tf32 bits
__device__ float    g_k [SEQ * NKVH  * HDIM];   // GEMM out (fp32)
__device__ float    g_v [SEQ * NKVH  * HDIM];   // GEMM out (fp32)
__device__ unsigned g_ao[SEQ * NHEAD * HDIM];   // attention out (tf32 bits)
__device__ unsigned g_ht[SEQ * HID];            // hidden, tf32 bits
__device__ unsigned g_wq[HID * NHEAD * HDIM];
__device__ unsigned g_wk[HID * NKVH  * HDIM];
__device__ unsigned g_wv[HID * NKVH  * HDIM];
__device__ unsigned g_wo[NHEAD * HDIM * HID];
__device__ unsigned g_kc[NKVH * KVTOT * HDIM];  // unified K (ret + new), token-major, tf32
__device__ unsigned g_vt[NKVH * HDIM * KVTOT];  // unified V transposed [hk][d][token], tf32

// ---------------- helpers ----------------
__device__ __forceinline__ unsigned f2tf(float x) {
    unsigned r;
    asm("cvt.rna.tf32.f32 %0, %1;" : "=r"(r) : "f"(x));
    return r;
}
__device__ __forceinline__ void mma8(float* c, const unsigned* a, const unsigned* b) {
    asm volatile(
        "mma.sync.aligned.m16n8k8.row.col.f32.tf32.tf32.f32 "
        "{%0,%1,%2,%3},{%4,%5,%6,%7},{%8,%9},{%0,%1,%2,%3};"
        : "+f"(c[0]), "+f"(c[1]), "+f"(c[2]), "+f"(c[3])
        : "r"(a[0]), "r"(a[1]), "r"(a[2]), "r"(a[3]), "r"(b[0]), "r"(b[1]));
}
__device__ __forceinline__ void ldsm_x4(unsigned* r, unsigned addr) {
    asm volatile("ldmatrix.sync.aligned.m8n8.x4.shared.b16 {%0,%1,%2,%3}, [%4];"
        : "=r"(r[0]), "=r"(r[1]), "=r"(r[2]), "=r"(r[3]) : "r"(addr));
}
#define CP16(dst, src) asm volatile("cp.async.cg.shared.global [%0], [%1], 16;" :: "r"(dst), "l"(src))
#define CP_COMMIT()    asm volatile("cp.async.commit_group;")
#define CP_WAIT0()     asm volatile("cp.async.wait_group 0;")
#define CP_WAIT1()     asm volatile("cp.async.wait_group 1;")

// ================= conversion kernels =================
__global__ void conv_tf32(const float4* __restrict__ in, uint4* __restrict__ out, int n4) {
    int i = blockIdx.x * blockDim.x + threadIdx.x;
    if (i < n4) {
        float4 v = in[i];
        out[i] = make_uint4(f2tf(v.x), f2tf(v.y), f2tf(v.z), f2tf(v.w));
    }
}

// rope + scale + tf32 on q, in place (bits stored into float array)
__global__ void rope_q(float* __restrict__ q, const float* __restrict__ cosb,
                       const float* __restrict__ sinb) {
    int id = blockIdx.x * blockDim.x + threadIdx.x;
    if (id >= SEQ * NHEAD * 32) return;
    int i = id & 31, h = (id >> 5) & 31, tok = id >> 10;
    float* base = q + (size_t)tok * (NHEAD * HDIM) + h * HDIM;
    float c0 = cosb[tok * 64 + i], c1 = cosb[tok * 64 + 32 + i];
    float s0 = sinb[tok * 64 + i], s1 = sinb[tok * 64 + 32 + i];
    float x0 = base[i], x1 = base[i + 32];
    ((unsigned*)base)[i]      = f2tf((x0 * c0 - x1 * s0) * SCALE);
    ((unsigned*)base)[i + 32] = f2tf((x1 * c1 + x0 * s1) * SCALE);
}

// rope + tf32 on k -> g_kc new-token region [hk][1024+tok][d]
__global__ void rope_pack_k(const float* __restrict__ k, const float* __restrict__ cosb,
                            const float* __restrict__ sinb, unsigned* __restrict__ kc) {
    int id = blockIdx.x * blockDim.x + threadIdx.x;
    if (id >= SEQ * NKVH * 32) return;
    int i = id & 31, hk = (id >> 5) & 7, tok = id >> 8;
    const float* base = k + (size_t)tok * (NKVH * HDIM) + hk * HDIM;
    float c0 = cosb[tok * 64 + i], c1 = cosb[tok * 64 + 32 + i];
    float s0 = sinb[tok * 64 + i], s1 = sinb[tok * 64 + 32 + i];
    float x0 = base[i], x1 = base[i + 32];
    unsigned* dst = kc + (size_t)hk * KVTOT * HDIM + (size_t)(RLEN + tok) * HDIM;
    dst[i]      = f2tf(x0 * c0 - x1 * s0);
    dst[i + 32] = f2tf(x1 * c1 + x0 * s1);
}

// retrieval K -> g_kc ret region [hk][0..1023][d]
__global__ void conv_rk(const float* __restrict__ rk, unsigned* __restrict__ kc) {
    int id = blockIdx.x * blockDim.x + threadIdx.x;
    if (id >= NKVH * RLEN * (HDIM / 4)) return;
    int hk = id >> 14, rem = id & 16383;
    int r = rem >> 4, d4 = (rem & 15) * 4;
    float4 v = *(const float4*)&rk[((size_t)hk * RLEN + r) * HDIM + d4];
    *(uint4*)&kc[(size_t)hk * KVTOT * HDIM + (size_t)r * HDIM + d4] =
        make_uint4(f2tf(v.x), f2tf(v.y), f2tf(v.z), f2tf(v.w));
}

// V (ret + new) -> transposed g_vt[hk][d][token], tf32.  grid (48 token-tiles, 8 hk)
__global__ __launch_bounds__(256) void pack_v(const float* __restrict__ v,
                                              const float* __restrict__ rv,
                                              unsigned* __restrict__ vt) {
    __shared__ float sm[64][65];
    const int tt = blockIdx.x, hk = blockIdx.y, tid = threadIdx.x;
    for (int i = tid; i < 4096; i += 256) {
        int r = i >> 6, c = i & 63;
        float val;
        if (tt < 16) {
            val = rv[((size_t)hk * RLEN + tt * 64 + r) * HDIM + c];
        } else {
            val = v[(size_t)((tt - 16) * 64 + r) * (NKVH * HDIM) + hk * HDIM + c];
        }
        sm[r][c] = val;
    }
    __syncthreads();
    for (int i = tid; i < 4096; i += 256) {
        int d = i >> 6, tok = i & 63;
        vt[(size_t)hk * HDIM * KVTOT + (size_t)d * KVTOT + tt * 64 + tok] = f2tf(sm[tok][d]);
    }
}

// ================= tf32 GEMM, cp.async double-buffered, ldmatrix A-frags =================
// C(MxN) = A(MxK) @ B(KxN), A/B pre-converted tf32 bits. BM=128 BN=128 BK=16, 256 thr = 8 warps.
constexpr int AS_STRIDE = 20;                 // words; %32==20 -> ldmatrix conflict-free, 16B aligned
constexpr int AS_WORDS  = 128 * AS_STRIDE;    // per stage
constexpr int BS_STRIDE = 136;                // %32==8 -> LDS B-frag conflict-free
constexpr int BS_WORDS  = 16 * BS_STRIDE;

__global__ __launch_bounds__(256)
void tc_gemm(const unsigned* __restrict__ A, const unsigned* __restrict__ B,
             float* __restrict__ C, int M, int N, int K)
{
    __shared__ unsigned As[2][AS_WORDS];
    __shared__ unsigned Bs[2][BS_WORDS];

    const int bm = blockIdx.y * 128;
    const int bn = blockIdx.x * 128;
    const int tid  = threadIdx.x;
    const int warp = tid >> 5;
    const int lane = tid & 31;
    const int gid  = lane >> 2;
    const int tig  = lane & 3;
    const int m_base = (warp >> 1) * 32;
    const int n_base = (warp & 1) * 64;
    // ldmatrix per-lane offsets (A-frag)
    const int lrow = ((lane >> 3) & 1) * 8 + (lane & 7);
    const int lcol = (lane >> 4) * 4;

    const unsigned as_u = (unsigned)__cvta_generic_to_shared(As);
    const unsigned bs_u = (unsigned)__cvta_generic_to_shared(Bs);

    // cp.async mappings
    const int am = tid >> 2, ak4 = (tid & 3) * 4;        // A: rows am, am+64
    const int bk = tid >> 4, bn4 = (tid & 15) * 4;       // B: cols bn4, bn4+64

    const int niter = K >> 4;

    auto issue = [&](int it, int s) {
        const size_t k0 = (size_t)it * 16;
        unsigned ad = as_u + (s * AS_WORDS + am * AS_STRIDE + ak4) * 4;
        CP16(ad, &A[(size_t)(bm + am) * K + k0 + ak4]);
        CP16(ad + 64 * AS_STRIDE * 4, &A[(size_t)(bm + am + 64) * K + k0 + ak4]);
        unsigned bd = bs_u + (s * BS_WORDS + bk * BS_STRIDE + bn4) * 4;
        CP16(bd, &B[(k0 + bk) * N + bn + bn4]);
        CP16(bd + 64 * 4, &B[(k0 + bk) * N + bn + bn4 + 64]);
    };

    float acc[2][8][4];
#pragma unroll
    for (int mt = 0; mt < 2; mt++)
#pragma unroll
        for (int nt = 0; nt < 8; nt++)
#pragma unroll
            for (int j = 0; j < 4; j++) acc[mt][nt][j] = 0.f;

    issue(0, 0);
    CP_COMMIT();

    for (int it = 0; it < niter; it++) {
        const int s = it & 1;
        if (it + 1 < niter) { issue(it + 1, s ^ 1); CP_COMMIT(); CP_WAIT1(); }
        else                { CP_WAIT0(); }
        __syncthreads();

#pragma unroll
        for (int ks = 0; ks < 2; ks++) {
            const int kb = ks * 8;
            unsigned a[2][4];
#pragma unroll
            for (int mt = 0; mt < 2; mt++)
                ldsm_x4(a[mt], as_u + (s * AS_WORDS + (m_base + mt * 16 + lrow) * AS_STRIDE + kb + lcol) * 4);
#pragma unroll
            for (int nt = 0; nt < 8; nt++) {
                unsigned b[2];
                b[0] = Bs[s][(kb + tig    ) * BS_STRIDE + n_base + nt * 8 + gid];
                b[1] = Bs[s][(kb + tig + 4) * BS_STRIDE + n_base + nt * 8 + gid];
                mma8(acc[0][nt], a[0], b);
                mma8(acc[1][nt], a[1], b);
            }
        }
        __syncthreads();
    }

#pragma unroll
    for (int mt = 0; mt < 2; mt++)
#pragma unroll
        for (int nt = 0; nt < 8; nt++) {
            int row = bm + m_base + mt * 16 + gid;
            int col = bn + n_base + nt * 8 + 2 * tig;
            *(float2*)&C[(size_t)row * N + col]       = make_float2(acc[mt][nt][0], acc[mt][nt][1]);
            *(float2*)&C[(size_t)(row + 8) * N + col] = make_float2(acc[mt][nt][2], acc[mt][nt][3]);
        }
}

// ================= tensor-core flash attention =================
// 128 threads = 4 warps; warp w owns q rows [16w,16w+16). Double-buffered K/V via cp.async.
// smem (words): Qs[64*68] @0, Ps[64*68] @4352, stage s: K @8704+s*8704, V @+4352.
constexpr int ATT_STR  = 68;                 // %32==4, 16B aligned -> ldmatrix conflict-free
constexpr int ATT_TILE = 64 * ATT_STR;       // 4352 words
constexpr int ATT_QS = 0;
constexpr int ATT_PS = ATT_TILE;
constexpr int ATT_KV = 2 * ATT_TILE;         // stage s at ATT_KV + s*2*ATT_TILE (K), +ATT_TILE (V)
constexpr int ATT_SMEM_BYTES = (2 * ATT_TILE + 2 * 2 * ATT_TILE) * 4;  // 104448

__global__ __launch_bounds__(128)
void attn_tc(const unsigned* __restrict__ q, const unsigned* __restrict__ kc,
             const unsigned* __restrict__ vt, unsigned* __restrict__ out)
{
    extern __shared__ unsigned sm[];
    const unsigned sm_u = (unsigned)__cvta_generic_to_shared(sm);

    const int t  = (int)gridDim.x - 1 - (int)blockIdx.x;
    const int h  = blockIdx.y;
    const int hk = h >> 2;
    const int tid  = threadIdx.x;
    const int warp = tid >> 5;
    const int lane = tid & 31;
    const int gid  = lane >> 2;
    const int tig  = lane & 3;
    const int q0 = warp * 16;
    const int lrow = ((lane >> 3) & 1) * 8 + (lane & 7);   // A-frag row offset
    const int lcol = (lane >> 4) * 4;                      // A-frag col offset
    const int brow = ((lane >> 4) << 3) + (lane & 7);      // B-frag row offset (within 16)
    const int bcol = ((lane >> 3) & 1) * 4;                // B-frag col offset

    const int hasret = (t >= 1) ? 1 : 0;
    const int ntiles = (t + 1) + hasret;
    const int rb = ((t < 16) ? t : 16) - 1;

    const unsigned* kbase = kc + (size_t)hk * KVTOT * HDIM;
    const unsigned* vbase = vt + (size_t)hk * HDIM * KVTOT;

    auto tokbase_of = [&](int it) {
        return (hasret && it == 0) ? rb * 64 : RLEN + (it - hasret) * 64;
    };
    auto issue_kv = [&](int it, int s) {
        const int tb = tokbase_of(it);
        const unsigned koff = sm_u + (ATT_KV + s * 2 * ATT_TILE) * 4;
        const unsigned voff = koff + ATT_TILE * 4;
#pragma unroll
        for (int j = 0; j < 8; j++) {
            int id = tid + j * 128;
            int r = id >> 4, c4 = (id & 15) * 4;
            CP16(koff + (r * ATT_STR + c4) * 4, &kbase[(size_t)(tb + r) * HDIM + c4]);
            CP16(voff + (r * ATT_STR + c4) * 4, &vbase[(size_t)r * KVTOT + tb + c4]);
        }
    };

    // prologue: Q + KV(0) in group 0
#pragma unroll
    for (int j = 0; j < 8; j++) {
        int id = tid + j * 128;
        int r = id >> 4, c4 = (id & 15) * 4;
        CP16(sm_u + (ATT_QS + r * ATT_STR + c4) * 4,
             &q[(size_t)(t * 64 + r) * (NHEAD * HDIM) + h * HDIM + c4]);
    }
    issue_kv(0, 0);
    CP_COMMIT();

    unsigned qa[8][4];
    float m_lo = -1e30f, m_hi = -1e30f, l_lo = 0.f, l_hi = 0.f;
    float O[8][4];
#pragma unroll
    for (int nt = 0; nt < 8; nt++)
#pragma unroll
        for (int j = 0; j < 4; j++) O[nt][j] = 0.f;

    for (int it = 0; it < ntiles; it++) {
        const int s = it & 1;
        const bool isret = hasret && (it == 0);
        const int jt = it - hasret;

        if (it + 1 < ntiles) { issue_kv(it + 1, s ^ 1); CP_COMMIT(); CP_WAIT1(); }
        else                 { CP_WAIT0(); }
        __syncthreads();

        if (it == 0) {
            // hoist Q A-frags into registers (tile-invariant)
#pragma unroll
            for (int kt = 0; kt < 8; kt++)
                ldsm_x4(qa[kt], sm_u + (ATT_QS + (q0 + lrow) * ATT_STR + kt * 8 + lcol) * 4);
        }

        const unsigned koff = sm_u + (ATT_KV + s * 2 * ATT_TILE) * 4;
        const unsigned voff = koff + ATT_TILE * 4;

        // S = Q K^T
        float sacc[8][4];
#pragma unroll
        for (int nt = 0; nt < 8; nt++)
#pragma unroll
            for (int j = 0; j < 4; j++) sacc[nt][j] = 0.f;

#pragma unroll
        for (int kt = 0; kt < 8; kt++) {
#pragma unroll
            for (int p = 0; p < 4; p++) {
                unsigned b[4];
                ldsm_x4(b, koff + ((p * 16 + brow) * ATT_STR + kt * 8 + bcol) * 4);
                mma8(sacc[2 * p],     qa[kt], b);
                mma8(sacc[2 * p + 1], qa[kt], b + 2);
            }
        }

        // mask (new-token tiles only; retrieval block fully valid)
        if (!isret) {
            const int s_lo = t * 64 + q0 + gid;
            const int s_hi = s_lo + 8;
#pragma unroll
            for (int nt = 0; nt < 8; nt++) {
#pragma unroll
                for (int j = 0; j < 2; j++) {
                    int n = jt * 64 + nt * 8 + 2 * tig + j;
                    bool inval = (n < 1);
                    if (inval || n > s_lo) sacc[nt][j]     = -1e30f;
                    if (inval || n > s_hi) sacc[nt][j + 2] = -1e30f;
                }
            }
        }

        // online softmax
        float lm_lo = -1e30f, lm_hi = -1e30f;
#pragma unroll
        for (int nt = 0; nt < 8; nt++) {
            lm_lo = fmaxf(lm_lo, fmaxf(sacc[nt][0], sacc[nt][1]));
            lm_hi = fmaxf(lm_hi, fmaxf(sacc[nt][2], sacc[nt][3]));
        }
        lm_lo = fmaxf(lm_lo, __shfl_xor_sync(0xffffffffu, lm_lo, 1));
        lm_lo = fmaxf(lm_lo, __shfl_xor_sync(0xffffffffu, lm_lo, 2));
        lm_hi = fmaxf(lm_hi, __shfl_xor_sync(0xffffffffu, lm_hi, 1));
        lm_hi = fmaxf(lm_hi, __shfl_xor_sync(0xffffffffu, lm_hi, 2));
        const float mn_lo = fmaxf(m_lo, lm_lo);
        const float mn_hi = fmaxf(m_hi, lm_hi);

        float sum_lo = 0.f, sum_hi = 0.f;
#pragma unroll
        for (int nt = 0; nt < 8; nt++) {
            float p00 = __expf(sacc[nt][0] - mn_lo);
            float p01 = __expf(sacc[nt][1] - mn_lo);
            float p10 = __expf(sacc[nt][2] - mn_hi);
            float p11 = __expf(sacc[nt][3] - mn_hi);
            sum_lo += p00 + p01;
            sum_hi += p10 + p11;
            *(uint2*)&sm[ATT_PS + (q0 + gid    ) * ATT_STR + nt * 8 + 2 * tig] =
                make_uint2(f2tf(p00), f2tf(p01));
            *(uint2*)&sm[ATT_PS + (q0 + gid + 8) * ATT_STR + nt * 8 + 2 * tig] =
                make_uint2(f2tf(p10), f2tf(p11));
        }
        sum_lo += __shfl_xor_sync(0xffffffffu, sum_lo, 1);
        sum_lo += __shfl_xor_sync(0xffffffffu, sum_lo, 2);
        sum_hi += __shfl_xor_sync(0xffffffffu, sum_hi, 1);
        sum_hi += __shfl_xor_sync(0xffffffffu, sum_hi, 2);

        const float f_lo = __expf(m_lo - mn_lo);
        const float f_hi = __expf(m_hi - mn_hi);
        m_lo = mn_lo; m_hi = mn_hi;
        l_lo = l_lo * f_lo + sum_lo;
        l_hi = l_hi * f_hi + sum_hi;
#pragma unroll
        for (int nt = 0; nt < 8; nt++) {
            O[nt][0] *= f_lo; O[nt][1] *= f_lo;
            O[nt][2] *= f_hi; O[nt][3] *= f_hi;
        }
        __syncwarp();   // Ps rows are warp-private

        // O += P @ V
#pragma unroll
        for (int kt = 0; kt < 8; kt++) {
            unsigned pa[4];
            ldsm_x4(pa, sm_u + (ATT_PS + (q0 + lrow) * ATT_STR + kt * 8 + lcol) * 4);
#pragma unroll
            for (int p = 0; p < 4; p++) {
                unsigned b[4];
                ldsm_x4(b, voff + ((p * 16 + brow) * ATT_STR + kt * 8 + bcol) * 4);
                mma8(O[2 * p],     pa, b);
                mma8(O[2 * p + 1], pa, b + 2);
            }
        }
        __syncthreads();   // stage reuse guard
    }

    // epilogue: write tf32 bits for the Wo GEMM
    const float inv_lo = (m_lo > -1e29f) ? (1.f / l_lo) : 0.f;
    const float inv_hi = (m_hi > -1e29f) ? (1.f / l_hi) : 0.f;
#pragma unroll
    for (int nt = 0; nt < 8; nt++) {
        int col = nt * 8 + 2 * tig;
        size_t r_lo = (size_t)(t * 64 + q0 + gid)     * (NHEAD * HDIM) + h * HDIM + col;
        size_t r_hi = (size_t)(t * 64 + q0 + gid + 8) * (NHEAD * HDIM) + h * HDIM + col;
        *(uint2*)&out[r_lo] = make_uint2(f2tf(O[nt][0] * inv_lo), f2tf(O[nt][1] * inv_lo));
        *(uint2*)&out[r_hi] = make_uint2(f2tf(O[nt][2] * inv_hi), f2tf(O[nt][3] * inv_hi));
    }
}

// ---------------- launch ----------------
extern "C" void kernel_launch(void* const* d_in, const int* in_sizes, int n_in,
                              void* d_out, int out_size)
{
    const float* hidden = (const float*)d_in[0];
    const float* cosb   = (const float*)d_in[1];
    const float* sinb   = (const float*)d_in[2];
    const float* rk     = (const float*)d_in[3];
    const float* rv     = (const float*)d_in[4];
    const float* Wq     = (const float*)d_in[5];
    const float* Wk     = (const float*)d_in[6];
    const float* Wv     = (const float*)d_in[7];
    const float* Wo     = (const float*)d_in[8];
    float* out = (float*)d_out;

    float *q, *k, *v;
    unsigned *ao, *ht, *wq, *wk, *wv, *wo, *kc, *vtp;
    cudaGetSymbolAddress((void**)&q,  g_q);
    cudaGetSymbolAddress((void**)&k,  g_k);
    cudaGetSymbolAddress((void**)&v,  g_v);
    cudaGetSymbolAddress((void**)&ao, g_ao);
    cudaGetSymbolAddress((void**)&ht, g_ht);
    cudaGetSymbolAddress((void**)&wq, g_wq);
    cudaGetSymbolAddress((void**)&wk, g_wk);
    cudaGetSymbolAddress((void**)&wv, g_wv);
    cudaGetSymbolAddress((void**)&wo, g_wo);
    cudaGetSymbolAddress((void**)&kc, g_kc);
    cudaGetSymbolAddress((void**)&vtp, g_vt);

    // 1. pre-convert operands to tf32
    auto conv = [&](const float* src, unsigned* dst, int n) {
        conv_tf32<<<(n / 4 + 255) / 256, 256>>>((const float4*)src, (uint4*)dst, n / 4);
    };
    conv(hidden, ht, SEQ * HID);
    conv(Wq, wq, HID * NHEAD * HDIM);
    conv(Wk, wk, HID * NKVH * HDIM);
    conv(Wv, wv, HID * NKVH * HDIM);
    conv(Wo, wo, NHEAD * HDIM * HID);

    // 2. projections
    tc_gemm<<<dim3((NHEAD * HDIM) / 128, SEQ / 128), 256>>>(ht, wq, q, SEQ, NHEAD * HDIM, HID);
    tc_gemm<<<dim3((NKVH  * HDIM) / 128, SEQ / 128), 256>>>(ht, wk, k, SEQ, NKVH * HDIM, HID);
    tc_gemm<<<dim3((NKVH  * HDIM) / 128, SEQ / 128), 256>>>(ht, wv, v, SEQ, NKVH * HDIM, HID);

    // 3. rope + pack K/V into unified tf32 buffers
    rope_q<<<(SEQ * NHEAD * 32 + 255) / 256, 256>>>(q, cosb, sinb);
    rope_pack_k<<<(SEQ * NKVH * 32 + 255) / 256, 256>>>(k, cosb, sinb, kc);
    conv_rk<<<(NKVH * RLEN * (HDIM / 4) + 255) / 256, 256>>>(rk, kc);
    pack_v<<<dim3(KVTOT / 64, NKVH), 256>>>(v, rv, vtp);

    // 4. attention
    cudaFuncSetAttribute(attn_tc, cudaFuncAttributeMaxDynamicSharedMemorySize, ATT_SMEM_BYTES);
    attn_tc<<<dim3(SEQ / 64, NHEAD), 128, ATT_SMEM_BYTES>>>((const unsigned*)q, kc, vtp, ao);

    // 5. output projection
    tc_gemm<<<dim3(HID / 128, SEQ / 128), 256>>>(ao, wo, out, SEQ, HID, HID);
}

// round 4
// speedup vs baseline: 6.7804x; 2.2420x over previous
#include <cuda_runtime.h>
#include <cuda_fp16.h>
#include <math.h>

// ---------------- problem constants ----------------
constexpr int SEQ  = 2048;
constexpr int HID  = 2048;
constexpr int NHEAD = 32;
constexpr int NKVH  = 8;
constexpr int HDIM  = 64;
constexpr int RLEN  = 1024;
constexpr int KVTOT = RLEN + SEQ;   // 3072
constexpr int NQKV  = NHEAD * HDIM + 2 * NKVH * HDIM;  // 3072
constexpr float SCALE = 0.125f;

// ---------------- scratch (device globals; no allocs) ----------------
__device__ __half g_hth [SEQ * HID];            // hidden fp16
__device__ __half g_wqkv[HID * NQKV];           // [k][n] Wq|Wk|Wv fp16
__device__ __half g_woh [HID * HID];            // Wo fp16 [k][n]
__device__ float  g_qkv [SEQ * NQKV];           // fused projection out (fp32)
__device__ __half g_qh  [SEQ * NHEAD * HDIM];   // roped Q fp16 (pre-scaled)
__device__ __half g_kc  [NKVH * KVTOT * HDIM];  // unified K [hk][tok][d] fp16
__device__ __half g_vt  [NKVH * HDIM * KVTOT];  // unified V [hk][d][tok] fp16
__device__ __half g_ao  [SEQ * NHEAD * HDIM];   // attention out fp16

// ---------------- helpers ----------------
__device__ __forceinline__ unsigned packh2(float x, float y) {
    __half2 h = __floats2half2_rn(x, y);
    return *(unsigned*)&h;
}
__device__ __forceinline__ void mma16(float* c, const unsigned* a, const unsigned* b) {
    asm volatile(
        "mma.sync.aligned.m16n8k16.row.col.f32.f16.f16.f32 "
        "{%0,%1,%2,%3},{%4,%5,%6,%7},{%8,%9},{%0,%1,%2,%3};"
        : "+f"(c[0]), "+f"(c[1]), "+f"(c[2]), "+f"(c[3])
        : "r"(a[0]), "r"(a[1]), "r"(a[2]), "r"(a[3]), "r"(b[0]), "r"(b[1]));
}
__device__ __forceinline__ void ldsm_x4(unsigned* r, unsigned addr) {
    asm volatile("ldmatrix.sync.aligned.m8n8.x4.shared.b16 {%0,%1,%2,%3}, [%4];"
        : "=r"(r[0]), "=r"(r[1]), "=r"(r[2]), "=r"(r[3]) : "r"(addr));
}
__device__ __forceinline__ void ldsm_x4_t(unsigned* r, unsigned addr) {
    asm volatile("ldmatrix.sync.aligned.m8n8.x4.trans.shared.b16 {%0,%1,%2,%3}, [%4];"
        : "=r"(r[0]), "=r"(r[1]), "=r"(r[2]), "=r"(r[3]) : "r"(addr));
}
#define CP16(dst, src) asm volatile("cp.async.cg.shared.global [%0], [%1], 16;" :: "r"(dst), "l"(src))
#define CP_COMMIT()    asm volatile("cp.async.commit_group;")
#define CP_WAIT0()     asm volatile("cp.async.wait_group 0;")
#define CP_WAIT1()     asm volatile("cp.async.wait_group 1;")

// ================= conversion kernels =================
// plain fp32 -> fp16 (n multiple of 8)
__global__ void conv_h(const float4* __restrict__ in, uint4* __restrict__ out, int n8) {
    int i = blockIdx.x * blockDim.x + threadIdx.x;
    if (i >= n8) return;
    float4 a = in[2 * i], b = in[2 * i + 1];
    out[i] = make_uint4(packh2(a.x, a.y), packh2(a.z, a.w),
                        packh2(b.x, b.y), packh2(b.z, b.w));
}
// W [HID][ncols] fp32 -> g_wqkv[k][noff + n] fp16
__global__ void conv_wcat(const float* __restrict__ W, __half* __restrict__ dst,
                          int ncols, int noff) {
    int id = blockIdx.x * blockDim.x + threadIdx.x;
    int n4c = ncols >> 2;
    if (id >= HID * n4c) return;
    int k = id / n4c, n4 = (id % n4c) * 4;
    float4 v = *(const float4*)&W[(size_t)k * ncols + n4];
    *(uint2*)&dst[(size_t)k * NQKV + noff + n4] = make_uint2(packh2(v.x, v.y), packh2(v.z, v.w));
}

// rope + scale on q columns of g_qkv -> g_qh fp16
__global__ void rope_q(const float* __restrict__ qkv, __half* __restrict__ qh,
                       const float* __restrict__ cosb, const float* __restrict__ sinb) {
    int id = blockIdx.x * blockDim.x + threadIdx.x;
    if (id >= SEQ * NHEAD * 32) return;
    int i = id & 31, h = (id >> 5) & 31, tok = id >> 10;
    const float* base = qkv + (size_t)tok * NQKV + h * HDIM;
    float c0 = cosb[tok * 64 + i], c1 = cosb[tok * 64 + 32 + i];
    float s0 = sinb[tok * 64 + i], s1 = sinb[tok * 64 + 32 + i];
    float x0 = base[i], x1 = base[i + 32];
    __half* dst = qh + (size_t)tok * (NHEAD * HDIM) + h * HDIM;
    dst[i]      = __float2half_rn((x0 * c0 - x1 * s0) * SCALE);
    dst[i + 32] = __float2half_rn((x1 * c1 + x0 * s1) * SCALE);
}

// rope on k columns of g_qkv -> g_kc new-token region
__global__ void rope_pack_k(const float* __restrict__ qkv, __half* __restrict__ kc,
                            const float* __restrict__ cosb, const float* __restrict__ sinb) {
    int id = blockIdx.x * blockDim.x + threadIdx.x;
    if (id >= SEQ * NKVH * 32) return;
    int i = id & 31, hk = (id >> 5) & 7, tok = id >> 8;
    const float* base = qkv + (size_t)tok * NQKV + NHEAD * HDIM + hk * HDIM;
    float c0 = cosb[tok * 64 + i], c1 = cosb[tok * 64 + 32 + i];
    float s0 = sinb[tok * 64 + i], s1 = sinb[tok * 64 + 32 + i];
    float x0 = base[i], x1 = base[i + 32];
    __half* dst = kc + (size_t)hk * KVTOT * HDIM + (size_t)(RLEN + tok) * HDIM;
    dst[i]      = __float2half_rn(x0 * c0 - x1 * s0);
    dst[i + 32] = __float2half_rn(x1 * c1 + x0 * s1);
}

// retrieval K fp32 -> g_kc ret region
__global__ void conv_rk(const float* __restrict__ rk, __half* __restrict__ kc) {
    int id = blockIdx.x * blockDim.x + threadIdx.x;
    if (id >= NKVH * RLEN * (HDIM / 4)) return;
    int hk = id >> 14, rem = id & 16383;
    int r = rem >> 4, d4 = (rem & 15) * 4;
    float4 v = *(const float4*)&rk[((size_t)hk * RLEN + r) * HDIM + d4];
    *(uint2*)&kc[(size_t)hk * KVTOT * HDIM + (size_t)r * HDIM + d4] =
        make_uint2(packh2(v.x, v.y), packh2(v.z, v.w));
}

// V (ret fp32 + new from g_qkv) -> transposed g_vt[hk][d][tok] fp16
__global__ __launch_bounds__(256) void pack_v(const float* __restrict__ qkv,
                                              const float* __restrict__ rv,
                                              __half* __restrict__ vt) {
    __shared__ float sm[64][65];
    const int tt = blockIdx.x, hk = blockIdx.y, tid = threadIdx.x;
    for (int i = tid; i < 4096; i += 256) {
        int r = i >> 6, c = i & 63;
        float val;
        if (tt < 16) {
            val = rv[((size_t)hk * RLEN + tt * 64 + r) * HDIM + c];
        } else {
            val = qkv[(size_t)((tt - 16) * 64 + r) * NQKV + NHEAD * HDIM + NKVH * HDIM + hk * HDIM + c];
        }
        sm[r][c] = val;
    }
    __syncthreads();
    for (int i = tid; i < 4096; i += 256) {
        int d = i >> 6, tok = i & 63;
        vt[(size_t)hk * HDIM * KVTOT + (size_t)d * KVTOT + tt * 64 + tok] =
            __float2half_rn(sm[tok][d]);
    }
}

// ================= fp16 GEMM: C(f32) = A(MxK,f16,row) @ B(KxN,f16,row) =================
// BM=128 BN=128 BK=32, 256 thr = 8 warps (4m x 2n), warp tile 32x64, m16n8k16.
constexpr int GA_STR = 40;             // halfwords; rows differ by 80B=5x16B -> ldsm conflict-free
constexpr int GB_STR = 136;            // halfwords; rows differ by 272B=17x16B -> conflict-free
constexpr int GA_HW  = 128 * GA_STR;   // per stage
constexpr int GB_HW  = 32 * GB_STR;

__global__ __launch_bounds__(256)
void hgemm(const __half* __restrict__ A, const __half* __restrict__ B,
           float* __restrict__ C, int M, int N, int K)
{
    __shared__ __half As[2][GA_HW];
    __shared__ __half Bs[2][GB_HW];

    const int bm = blockIdx.y * 128;
    const int bn = blockIdx.x * 128;
    const int tid  = threadIdx.x;
    const int warp = tid >> 5;
    const int lane = tid & 31;
    const int gid  = lane >> 2;
    const int tig  = lane & 3;
    const int m_base = (warp >> 1) * 32;
    const int n_base = (warp & 1) * 64;

    const unsigned as_u = (unsigned)__cvta_generic_to_shared(As);
    const unsigned bs_u = (unsigned)__cvta_generic_to_shared(Bs);

    const int aRow = tid >> 2, aC = (tid & 3) * 8;
    const int bK   = tid >> 4, bN = (tid & 15) * 8;

    // ldmatrix lane addressing
    const int a_r = lane & 15, a_c = (lane >> 4) << 3;                    // A frag
    const int b_k = ((lane >> 3) & 1) * 8 + (lane & 7), b_n = (lane >> 4) << 3;  // B frag (trans)

    const int niter = K >> 5;

    auto issue = [&](int it, int s) {
        const size_t k0 = (size_t)it * 32;
        unsigned ad = as_u + (s * GA_HW + aRow * GA_STR + aC) * 2;
        CP16(ad,                       &A[(size_t)(bm + aRow) * K + k0 + aC]);
        CP16(ad + 64 * GA_STR * 2,     &A[(size_t)(bm + aRow + 64) * K + k0 + aC]);
        unsigned bd = bs_u + (s * GB_HW + bK * GB_STR + bN) * 2;
        CP16(bd,                       &B[(k0 + bK) * N + bn + bN]);
        CP16(bd + 16 * GB_STR * 2,     &B[(k0 + bK + 16) * N + bn + bN]);
    };

    float acc[2][8][4];
#pragma unroll
    for (int mt = 0; mt < 2; mt++)
#pragma unroll
        for (int nt = 0; nt < 8; nt++)
#pragma unroll
            for (int j = 0; j < 4; j++) acc[mt][nt][j] = 0.f;

    issue(0, 0);
    CP_COMMIT();

    for (int it = 0; it < niter; it++) {
        const int s = it & 1;
        if (it + 1 < niter) { issue(it + 1, s ^ 1); CP_COMMIT(); CP_WAIT1(); }
        else                { CP_WAIT0(); }
        __syncthreads();

#pragma unroll
        for (int ks = 0; ks < 2; ks++) {
            const int kb = ks * 16;
            unsigned a[2][4];
#pragma unroll
            for (int mt = 0; mt < 2; mt++)
                ldsm_x4(a[mt], as_u + (s * GA_HW + (m_base + mt * 16 + a_r) * GA_STR + kb + a_c) * 2);
#pragma unroll
            for (int ng = 0; ng < 4; ng++) {
                unsigned b4[4];
                ldsm_x4_t(b4, bs_u + (s * GB_HW + (kb + b_k) * GB_STR + n_base + ng * 16 + b_n) * 2);
                mma16(acc[0][ng * 2],     a[0], b4);
                mma16(acc[0][ng * 2 + 1], a[0], b4 + 2);
                mma16(acc[1][ng * 2],     a[1], b4);
                mma16(acc[1][ng * 2 + 1], a[1], b4 + 2);
            }
        }
        __syncthreads();
    }

#pragma unroll
    for (int mt = 0; mt < 2; mt++)
#pragma unroll
        for (int nt = 0; nt < 8; nt++) {
            int row = bm + m_base + mt * 16 + gid;
            int col = bn + n_base + nt * 8 + 2 * tig;
            *(float2*)&C[(size_t)row * N + col]       = make_float2(acc[mt][nt][0], acc[mt][nt][1]);
            *(float2*)&C[(size_t)(row + 8) * N + col] = make_float2(acc[mt][nt][2], acc[mt][nt][3]);
        }
}

// ================= fp16 tensor-core flash attention =================
// 128 thr = 4 warps; warp w owns q rows [16w,16w+16). Double-buffered K/V (cp.async).
// P never touches smem (C-frag == next A-frag layout for fp16).
constexpr int AT_STR = 72;                 // halfwords; 144B = 9x16B -> ldsm conflict-free
constexpr int AT_HW  = 64 * AT_STR;        // 4608 hw per tile
constexpr int ATT_SMEM_BYTES = (AT_HW * 5) * 2;  // Q + 2 stages x (K,V) = 46080 B

__global__ __launch_bounds__(128)
void attn_tc(const __half* __restrict__ qh, const __half* __restrict__ kc,
             const __half* __restrict__ vt, __half* __restrict__ out)
{
    extern __shared__ __half sm[];
    const unsigned sm_u = (unsigned)__cvta_generic_to_shared(sm);

    const int t  = (int)gridDim.x - 1 - (int)blockIdx.x;
    const int h  = blockIdx.y;
    const int hk = h >> 2;
    const int tid  = threadIdx.x;
    const int warp = tid >> 5;
    const int lane = tid & 31;
    const int gid  = lane >> 2;
    const int tig  = lane & 3;
    const int q0 = warp * 16;

    const int a_r = lane & 15, a_c = (lane >> 4) << 3;                         // A frag lanes
    const int b_r = ((lane >> 4) << 3) + (lane & 7), b_c = ((lane >> 3) & 1) * 8;  // B frag (non-trans)

    const int hasret = (t >= 1) ? 1 : 0;
    const int ntiles = (t + 1) + hasret;
    const int rb = ((t < 16) ? t : 16) - 1;

    const __half* kbase = kc + (size_t)hk * KVTOT * HDIM;
    const __half* vbase = vt + (size_t)hk * HDIM * KVTOT;

    auto tokbase_of = [&](int it) {
        return (hasret && it == 0) ? rb * 64 : RLEN + (it - hasret) * 64;
    };
    auto issue_kv = [&](int it, int s) {
        const int tb = tokbase_of(it);
        const unsigned koff = sm_u + (AT_HW + s * 2 * AT_HW) * 2;
        const unsigned voff = koff + AT_HW * 2;
#pragma unroll
        for (int j = 0; j < 4; j++) {
            int id = tid + j * 128;
            int r = id >> 3, c8 = (id & 7) * 8;
            CP16(koff + (r * AT_STR + c8) * 2, &kbase[(size_t)(tb + r) * HDIM + c8]);
            CP16(voff + (r * AT_STR + c8) * 2, &vbase[(size_t)r * KVTOT + tb + c8]);
        }
    };

    // prologue: Q + KV(0)
#pragma unroll
    for (int j = 0; j < 4; j++) {
        int id = tid + j * 128;
        int r = id >> 3, c8 = (id & 7) * 8;
        CP16(sm_u + (r * AT_STR + c8) * 2,
             &qh[(size_t)(t * 64 + r) * (NHEAD * HDIM) + h * HDIM + c8]);
    }
    issue_kv(0, 0);
    CP_COMMIT();

    unsigned qa[4][4];
    float m_lo = -1e30f, m_hi = -1e30f, l_lo = 0.f, l_hi = 0.f;
    float O[8][4];
#pragma unroll
    for (int nt = 0; nt < 8; nt++)
#pragma unroll
        for (int j = 0; j < 4; j++) O[nt][j] = 0.f;

    for (int it = 0; it < ntiles; it++) {
        const int s = it & 1;
        const bool isret = hasret && (it == 0);
        const int jt = it - hasret;

        if (it + 1 < ntiles) { issue_kv(it + 1, s ^ 1); CP_COMMIT(); CP_WAIT1(); }
        else                 { CP_WAIT0(); }
        __syncthreads();

        if (it == 0) {
#pragma unroll
            for (int kt = 0; kt < 4; kt++)
                ldsm_x4(qa[kt], sm_u + ((q0 + a_r) * AT_STR + kt * 16 + a_c) * 2);
        }

        const unsigned koff = sm_u + (AT_HW + s * 2 * AT_HW) * 2;
        const unsigned voff = koff + AT_HW * 2;

        // S = Q K^T
        float sacc[8][4];
#pragma unroll
        for (int nt = 0; nt < 8; nt++)
#pragma unroll
            for (int j = 0; j < 4; j++) sacc[nt][j] = 0.f;

#pragma unroll
        for (int kt = 0; kt < 4; kt++) {
            const int kb = kt * 16;
#pragma unroll
            for (int ng = 0; ng < 4; ng++) {
                unsigned b4[4];
                ldsm_x4(b4, koff + ((ng * 16 + b_r) * AT_STR + kb + b_c) * 2);
                mma16(sacc[ng * 2],     qa[kt], b4);
                mma16(sacc[ng * 2 + 1], qa[kt], b4 + 2);
            }
        }

        // mask (new-token tiles only; retrieval block fully valid)
        if (!isret) {
            const int s_lo = t * 64 + q0 + gid;
            const int s_hi = s_lo + 8;
#pragma unroll
            for (int nt = 0; nt < 8; nt++) {
#pragma unroll
                for (int j = 0; j < 2; j++) {
                    int n = jt * 64 + nt * 8 + 2 * tig + j;
                    bool inval = (n < 1);
                    if (inval || n > s_lo) sacc[nt][j]     = -1e30f;
                    if (inval || n > s_hi) sacc[nt][j + 2] = -1e30f;
                }
            }
        }

        // online softmax
        float lm_lo = -1e30f, lm_hi = -1e30f;
#pragma unroll
        for (int nt = 0; nt < 8; nt++) {
            lm_lo = fmaxf(lm_lo, fmaxf(sacc[nt][0], sacc[nt][1]));
            lm_hi = fmaxf(lm_hi, fmaxf(sacc[nt][2], sacc[nt][3]));
        }
        lm_lo = fmaxf(lm_lo, __shfl_xor_sync(0xffffffffu, lm_lo, 1));
        lm_lo = fmaxf(lm_lo, __shfl_xor_sync(0xffffffffu, lm_lo, 2));
        lm_hi = fmaxf(lm_hi, __shfl_xor_sync(0xffffffffu, lm_hi, 1));
        lm_hi = fmaxf(lm_hi, __shfl_xor_sync(0xffffffffu, lm_hi, 2));
        const float mn_lo = fmaxf(m_lo, lm_lo);
        const float mn_hi = fmaxf(m_hi, lm_hi);

        float sum_lo = 0.f, sum_hi = 0.f;
#pragma unroll
        for (int nt = 0; nt < 8; nt++) {
            sacc[nt][0] = __expf(sacc[nt][0] - mn_lo);
            sacc[nt][1] = __expf(sacc[nt][1] - mn_lo);
            sacc[nt][2] = __expf(sacc[nt][2] - mn_hi);
            sacc[nt][3] = __expf(sacc[nt][3] - mn_hi);
            sum_lo += sacc[nt][0] + sacc[nt][1];
            sum_hi += sacc[nt][2] + sacc[nt][3];
        }
        sum_lo += __shfl_xor_sync(0xffffffffu, sum_lo, 1);
        sum_lo += __shfl_xor_sync(0xffffffffu, sum_lo, 2);
        sum_hi += __shfl_xor_sync(0xffffffffu, sum_hi, 1);
        sum_hi += __shfl_xor_sync(0xffffffffu, sum_hi, 2);

        const float f_lo = __expf(m_lo - mn_lo);
        const float f_hi = __expf(m_hi - mn_hi);
        m_lo = mn_lo; m_hi = mn_hi;
        l_lo = l_lo * f_lo + sum_lo;
        l_hi = l_hi * f_hi + sum_hi;
#pragma unroll
        for (int nt = 0; nt < 8; nt++) {
            O[nt][0] *= f_lo; O[nt][1] *= f_lo;
            O[nt][2] *= f_hi; O[nt][3] *= f_hi;
        }

        // O += P @ V   (P packed straight from C-frags into A-frags)
#pragma unroll
        for (int kt = 0; kt < 4; kt++) {
            unsigned pa[4];
            pa[0] = packh2(sacc[2 * kt][0],     sacc[2 * kt][1]);
            pa[1] = packh2(sacc[2 * kt][2],     sacc[2 * kt][3]);
            pa[2] = packh2(sacc[2 * kt + 1][0], sacc[2 * kt + 1][1]);
            pa[3] = packh2(sacc[2 * kt + 1][2], sacc[2 * kt + 1][3]);
#pragma unroll
            for (int ng = 0; ng < 4; ng++) {
                unsigned b4[4];
                ldsm_x4(b4, voff + ((ng * 16 + b_r) * AT_STR + kt * 16 + b_c) * 2);
                mma16(O[ng * 2],     pa, b4);
                mma16(O[ng * 2 + 1], pa, b4 + 2);
            }
        }
        __syncthreads();   // stage reuse guard
    }

    // epilogue: fp16 out for the Wo GEMM
    const float inv_lo = (m_lo > -1e29f) ? (1.f / l_lo) : 0.f;
    const float inv_hi = (m_hi > -1e29f) ? (1.f / l_hi) : 0.f;
#pragma unroll
    for (int nt = 0; nt < 8; nt++) {
        int col = nt * 8 + 2 * tig;
        size_t r_lo = (size_t)(t * 64 + q0 + gid)     * (NHEAD * HDIM) + h * HDIM + col;
        size_t r_hi = (size_t)(t * 64 + q0 + gid + 8) * (NHEAD * HDIM) + h * HDIM + col;
        *(unsigned*)&out[r_lo] = packh2(O[nt][0] * inv_lo, O[nt][1] * inv_lo);
        *(unsigned*)&out[r_hi] = packh2(O[nt][2] * inv_hi, O[nt][3] * inv_hi);
    }
}

// ---------------- launch ----------------
extern "C" void kernel_launch(void* const* d_in, const int* in_sizes, int n_in,
                              void* d_out, int out_size)
{
    const float* hidden = (const float*)d_in[0];
    const float* cosb   = (const float*)d_in[1];
    const float* sinb   = (const float*)d_in[2];
    const float* rk     = (const float*)d_in[3];
    const float* rv     = (const float*)d_in[4];
    const float* Wq     = (const float*)d_in[5];
    const float* Wk     = (const float*)d_in[6];
    const float* Wv     = (const float*)d_in[7];
    const float* Wo     = (const float*)d_in[8];
    float* out = (float*)d_out;

    __half *hth, *wqkv, *woh, *qh, *kc, *vtp, *ao;
    float *qkv;
    cudaGetSymbolAddress((void**)&hth,  g_hth);
    cudaGetSymbolAddress((void**)&wqkv, g_wqkv);
    cudaGetSymbolAddress((void**)&woh,  g_woh);
    cudaGetSymbolAddress((void**)&qkv,  g_qkv);
    cudaGetSymbolAddress((void**)&qh,   g_qh);
    cudaGetSymbolAddress((void**)&kc,   g_kc);
    cudaGetSymbolAddress((void**)&vtp,  g_vt);
    cudaGetSymbolAddress((void**)&ao,   g_ao);

    // 1. fp16 conversions
    conv_h<<<(SEQ * HID / 8 + 255) / 256, 256>>>((const float4*)hidden, (uint4*)hth, SEQ * HID / 8);
    conv_wcat<<<(HID * 512 + 255) / 256, 256>>>(Wq, wqkv, 2048, 0);
    conv_wcat<<<(HID * 128 + 255) / 256, 256>>>(Wk, wqkv, 512, 2048);
    conv_wcat<<<(HID * 128 + 255) / 256, 256>>>(Wv, wqkv, 512, 2560);
    conv_h<<<(HID * HID / 8 + 255) / 256, 256>>>((const float4*)Wo, (uint4*)woh, HID * HID / 8);

    // 2. fused QKV projection
    hgemm<<<dim3(NQKV / 128, SEQ / 128), 256>>>(hth, wqkv, qkv, SEQ, NQKV, HID);

    // 3. rope + pack
    rope_q<<<(SEQ * NHEAD * 32 + 255) / 256, 256>>>(qkv, qh, cosb, sinb);
    rope_pack_k<<<(SEQ * NKVH * 32 + 255) / 256, 256>>>(qkv, kc, cosb, sinb);
    conv_rk<<<(NKVH * RLEN * (HDIM / 4) + 255) / 256, 256>>>(rk, kc);
    pack_v<<<dim3(KVTOT / 64, NKVH), 256>>>(qkv, rv, vtp);

    // 4. attention
    cudaFuncSetAttribute(attn_tc, cudaFuncAttributeMaxDynamicSharedMemorySize, ATT_SMEM_BYTES);
    attn_tc<<<dim3(SEQ / 64, NHEAD), 128, ATT_SMEM_BYTES>>>(qh, kc, vtp, ao);

    // 5. output projection
    hgemm<<<dim3(HID / 128, SEQ / 128), 256>>>(ao, woh, out, SEQ, HID, HID);
}

// round 8
// speedup vs baseline: 7.3168x; 1.0791x over previous
#include <cuda_runtime.h>
#include <cuda_fp16.h>
#include <cstdint>

// ---------------- problem constants ----------------
constexpr int SEQ  = 2048;
constexpr int HID  = 2048;
constexpr int NHEAD = 32;
constexpr int NKVH  = 8;
constexpr int HDIM  = 64;
constexpr int RLEN  = 1024;
constexpr int KVTOT = RLEN + SEQ;   // 3072
constexpr int NQKV  = NHEAD * HDIM + 2 * NKVH * HDIM;  // 3072
constexpr float SCALE = 0.125f;

// ---------------- scratch (device globals; no allocs) ----------------
__device__ __half g_hth [SEQ * HID];            // hidden fp16
__device__ __half g_wqkv[HID * NQKV];           // Wq|Wk|Wv fp16 [k][n]
__device__ __half g_woh [HID * HID];            // Wo fp16 [k][n]
__device__ __half g_qh  [SEQ * NHEAD * HDIM];   // roped+scaled Q fp16
__device__ __half g_kc  [NKVH * KVTOT * HDIM];  // unified K [hk][tok][d] fp16
__device__ __half g_vn  [SEQ * NKVH * HDIM];    // new-token V fp16 [tok][hk*64+d]
__device__ __half g_vt  [NKVH * HDIM * KVTOT];  // unified V transposed [hk][d][tok]
__device__ __half g_ao  [SEQ * NHEAD * HDIM];   // attention out fp16

// ---------------- helpers ----------------
__device__ __forceinline__ unsigned packh2(float x, float y) {
    __half2 h = __floats2half2_rn(x, y);
    return *(unsigned*)&h;
}
__device__ __forceinline__ void mma16(float* c, const unsigned* a, const unsigned* b) {
    asm volatile(
        "mma.sync.aligned.m16n8k16.row.col.f32.f16.f16.f32 "
        "{%0,%1,%2,%3},{%4,%5,%6,%7},{%8,%9},{%0,%1,%2,%3};"
        : "+f"(c[0]), "+f"(c[1]), "+f"(c[2]), "+f"(c[3])
        : "r"(a[0]), "r"(a[1]), "r"(a[2]), "r"(a[3]), "r"(b[0]), "r"(b[1]));
}
__device__ __forceinline__ void ldsm_x4(unsigned* r, unsigned addr) {
    asm volatile("ldmatrix.sync.aligned.m8n8.x4.shared.b16 {%0,%1,%2,%3}, [%4];"
        : "=r"(r[0]), "=r"(r[1]), "=r"(r[2]), "=r"(r[3]) : "r"(addr));
}
__device__ __forceinline__ void ldsm_x4_t(unsigned* r, unsigned addr) {
    asm volatile("ldmatrix.sync.aligned.m8n8.x4.trans.shared.b16 {%0,%1,%2,%3}, [%4];"
        : "=r"(r[0]), "=r"(r[1]), "=r"(r[2]), "=r"(r[3]) : "r"(addr));
}
#define CP16(dst, src) asm volatile("cp.async.cg.shared.global [%0], [%1], 16;" :: "r"(dst), "l"(src))
#define CP_COMMIT()    asm volatile("cp.async.commit_group;")
#define CP_WAIT0()     asm volatile("cp.async.wait_group 0;")
#define CP_WAIT1()     asm volatile("cp.async.wait_group 1;")

// ================= conversion kernels =================
__global__ void conv_h(const float4* __restrict__ in, uint4* __restrict__ out, int n8) {
    int i = blockIdx.x * blockDim.x + threadIdx.x;
    if (i >= n8) return;
    float4 a = in[2 * i], b = in[2 * i + 1];
    out[i] = make_uint4(packh2(a.x, a.y), packh2(a.z, a.w),
                        packh2(b.x, b.y), packh2(b.z, b.w));
}
__global__ void conv_wcat(const float* __restrict__ W, __half* __restrict__ dst,
                          int ncols, int noff) {
    int id = blockIdx.x * blockDim.x + threadIdx.x;
    int n4c = ncols >> 2;
    if (id >= HID * n4c) return;
    int k = id / n4c, n4 = (id % n4c) * 4;
    float4 v = *(const float4*)&W[(size_t)k * ncols + n4];
    *(uint2*)&dst[(size_t)k * NQKV + noff + n4] = make_uint2(packh2(v.x, v.y), packh2(v.z, v.w));
}
__global__ void conv_rk(const float* __restrict__ rk, __half* __restrict__ kc) {
    int id = blockIdx.x * blockDim.x + threadIdx.x;
    if (id >= NKVH * RLEN * (HDIM / 4)) return;
    int hk = id >> 14, rem = id & 16383;
    int r = rem >> 4, d4 = (rem & 15) * 4;
    float4 v = *(const float4*)&rk[((size_t)hk * RLEN + r) * HDIM + d4];
    *(uint2*)&kc[(size_t)hk * KVTOT * HDIM + (size_t)r * HDIM + d4] =
        make_uint2(packh2(v.x, v.y), packh2(v.z, v.w));
}
// V (ret fp32 + new fp16) -> transposed g_vt[hk][d][tok]
__global__ __launch_bounds__(256)
void pack_v(const __half* __restrict__ vn, const float* __restrict__ rv,
            __half* __restrict__ vt) {
    __shared__ float sm[64][65];
    const int tt = blockIdx.x, hk = blockIdx.y, tid = threadIdx.x;
    for (int i = tid; i < 4096; i += 256) {
        int r = i >> 6, c = i & 63;
        float val;
        if (tt < 16) {
            val = rv[((size_t)hk * RLEN + tt * 64 + r) * HDIM + c];
        } else {
            val = __half2float(vn[(size_t)((tt - 16) * 64 + r) * 512 + hk * 64 + c]);
        }
        sm[r][c] = val;
    }
    __syncthreads();
    for (int i = tid; i < 4096; i += 256) {
        int d = i >> 6, tok = i & 63;
        vt[(size_t)hk * HDIM * KVTOT + (size_t)d * KVTOT + tt * 64 + tok] =
            __float2half_rn(sm[tok][d]);
    }
}

// ================= fp16 GEMM mainloop: 3-stage cp.async, BM=128 BN=128 BK=32 =================
constexpr int GA_STR = 40;             // halfwords
constexpr int GB_STR = 136;
constexpr int GA_HW  = 128 * GA_STR;   // per stage
constexpr int GB_HW  = 32 * GB_STR;
constexpr int SMEM_H = 3 * (GA_HW + GB_HW) * 2;   // 56832 B

__device__ __forceinline__ void hgemm_main(
    const __half* __restrict__ A, const __half* __restrict__ B,
    int K, int N, int bm, int bn, int tid,
    unsigned as_u, unsigned bs_u, float acc[2][8][4])
{
    const int warp = tid >> 5;
    const int lane = tid & 31;
    const int m_base = (warp >> 1) * 32;
    const int n_base = (warp & 1) * 64;

    const int aRow = tid >> 2, aC = (tid & 3) * 8;
    const int bK   = tid >> 4, bN = (tid & 15) * 8;

    const int a_r = lane & 15, a_c = (lane >> 4) << 3;
    const int b_k = ((lane >> 3) & 1) * 8 + (lane & 7), b_n = (lane >> 4) << 3;

    auto issue = [&](int it, int s) {
        const size_t k0 = (size_t)it * 32;
        unsigned ad = as_u + (s * GA_HW + aRow * GA_STR + aC) * 2;
        CP16(ad,                   &A[(size_t)(bm + aRow) * K + k0 + aC]);
        CP16(ad + 64 * GA_STR * 2, &A[(size_t)(bm + aRow + 64) * K + k0 + aC]);
        unsigned bd = bs_u + (s * GB_HW + bK * GB_STR + bN) * 2;
        CP16(bd,                   &B[(k0 + bK) * N + bn + bN]);
        CP16(bd + 16 * GB_STR * 2, &B[(k0 + bK + 16) * N + bn + bN]);
    };

#pragma unroll
    for (int mt = 0; mt < 2; mt++)
#pragma unroll
        for (int nt = 0; nt < 8; nt++)
#pragma unroll
            for (int j = 0; j < 4; j++) acc[mt][nt][j] = 0.f;

    const int niter = K >> 5;
    issue(0, 0); CP_COMMIT();
    issue(1, 1); CP_COMMIT();

    for (int it = 0; it < niter; it++) {
        const int s = it % 3;
        CP_WAIT1();
        __syncthreads();

#pragma unroll
        for (int ks = 0; ks < 2; ks++) {
            const int kb = ks * 16;
            unsigned a[2][4];
#pragma unroll
            for (int mt = 0; mt < 2; mt++)
                ldsm_x4(a[mt], as_u + (s * GA_HW + (m_base + mt * 16 + a_r) * GA_STR + kb + a_c) * 2);
#pragma unroll
            for (int ng = 0; ng < 4; ng++) {
                unsigned b4[4];
                ldsm_x4_t(b4, bs_u + (s * GB_HW + (kb + b_k) * GB_STR + n_base + ng * 16 + b_n) * 2);
                mma16(acc[0][ng * 2],     a[0], b4);
                mma16(acc[0][ng * 2 + 1], a[0], b4 + 2);
                mma16(acc[1][ng * 2],     a[1], b4);
                mma16(acc[1][ng * 2 + 1], a[1], b4 + 2);
            }
        }
        if (it + 2 < niter) issue(it + 2, (it + 2) % 3);
        CP_COMMIT();
    }
}

// ---- fused QKV GEMM: epilogue applies rope + fp16 pack, scatters to qh/kc/vn ----
__global__ __launch_bounds__(256)
void hgemm_qkv(const __half* __restrict__ A, const __half* __restrict__ B,
               const float* __restrict__ cosb, const float* __restrict__ sinb,
               __half* __restrict__ qh, __half* __restrict__ kc, __half* __restrict__ vn)
{
    extern __shared__ __half smh[];
    const unsigned as_u = (unsigned)__cvta_generic_to_shared(smh);
    const unsigned bs_u = as_u + 3 * GA_HW * 2;
    const int tid = threadIdx.x;
    const int bm = blockIdx.y * 128, bn = blockIdx.x * 128;

    float acc[2][8][4];
    hgemm_main(A, B, HID, NQKV, bm, bn, tid, as_u, bs_u, acc);

    const int warp = tid >> 5, lane = tid & 31;
    const int gid = lane >> 2, tig = lane & 3;
    const int m_base = (warp >> 1) * 32;
    const int n_warp0 = bn + (warp & 1) * 64;   // 64-aligned: one head, one region

    if (n_warp0 < 2560) {
        // q or k: rope pairs (i, i+32) are (nt, nt+4) in-thread
        const float sc = (n_warp0 < 2048) ? SCALE : 1.f;
#pragma unroll
        for (int mt = 0; mt < 2; mt++) {
#pragma unroll
            for (int half = 0; half < 2; half++) {
                const int row = bm + m_base + mt * 16 + gid + half * 8;   // token
                const int jo = half * 2;
#pragma unroll
                for (int nt = 0; nt < 4; nt++) {
                    const int i = nt * 8 + 2 * tig;
                    float2 cc = *(const float2*)&cosb[(size_t)row * 64 + i];
                    float2 ss = *(const float2*)&sinb[(size_t)row * 64 + i];
                    float x00 = acc[mt][nt][jo],     x01 = acc[mt][nt][jo + 1];
                    float x10 = acc[mt][nt + 4][jo], x11 = acc[mt][nt + 4][jo + 1];
                    unsigned lo = packh2((x00 * cc.x - x10 * ss.x) * sc,
                                         (x01 * cc.y - x11 * ss.y) * sc);
                    unsigned hi = packh2((x10 * cc.x + x00 * ss.x) * sc,
                                         (x11 * cc.y + x01 * ss.y) * sc);
                    __half* d0;
                    if (n_warp0 < 2048) {
                        d0 = qh + (size_t)row * 2048 + n_warp0 + i;
                    } else {
                        const int rel = n_warp0 - 2048 + i;
                        d0 = kc + ((size_t)(rel >> 6) * KVTOT + RLEN + row) * HDIM + (rel & 63);
                    }
                    *(unsigned*)d0        = lo;
                    *(unsigned*)(d0 + 32) = hi;
                }
            }
        }
    } else {
        // v region: plain fp16 store to vn[tok][512]
#pragma unroll
        for (int mt = 0; mt < 2; mt++) {
#pragma unroll
            for (int half = 0; half < 2; half++) {
                const int row = bm + m_base + mt * 16 + gid + half * 8;
                const int jo = half * 2;
#pragma unroll
                for (int nt = 0; nt < 8; nt++) {
                    const int col = n_warp0 + nt * 8 + 2 * tig - 2560;
                    *(unsigned*)&vn[(size_t)row * 512 + col] =
                        packh2(acc[mt][nt][jo], acc[mt][nt][jo + 1]);
                }
            }
        }
    }
}

// ---- Wo GEMM: fp32 out ----
__global__ __launch_bounds__(256)
void hgemm_out(const __half* __restrict__ A, const __half* __restrict__ B,
               float* __restrict__ C)
{
    extern __shared__ __half smh[];
    const unsigned as_u = (unsigned)__cvta_generic_to_shared(smh);
    const unsigned bs_u = as_u + 3 * GA_HW * 2;
    const int tid = threadIdx.x;
    const int bm = blockIdx.y * 128, bn = blockIdx.x * 128;

    float acc[2][8][4];
    hgemm_main(A, B, HID, HID, bm, bn, tid, as_u, bs_u, acc);

    const int warp = tid >> 5, lane = tid & 31;
    const int gid = lane >> 2, tig = lane & 3;
    const int m_base = (warp >> 1) * 32;
    const int n_base = (warp & 1) * 64;
#pragma unroll
    for (int mt = 0; mt < 2; mt++)
#pragma unroll
        for (int nt = 0; nt < 8; nt++) {
            int row = bm + m_base + mt * 16 + gid;
            int col = bn + n_base + nt * 8 + 2 * tig;
            *(float2*)&C[(size_t)row * HID + col]       = make_float2(acc[mt][nt][0], acc[mt][nt][1]);
            *(float2*)&C[(size_t)(row + 8) * HID + col] = make_float2(acc[mt][nt][2], acc[mt][nt][3]);
        }
}

// ================= fp16 mma.sync flash attention (R4, known-good) =================
constexpr int AT_STR = 72;
constexpr int AT_HW  = 64 * AT_STR;
constexpr int ATT_SMEM_BYTES = (AT_HW * 5) * 2;

__global__ __launch_bounds__(128)
void attn_tc(const __half* __restrict__ qh, const __half* __restrict__ kc,
             const __half* __restrict__ vt, __half* __restrict__ out)
{
    extern __shared__ __half sm[];
    const unsigned sm_u = (unsigned)__cvta_generic_to_shared(sm);

    const int t  = (int)gridDim.x - 1 - (int)blockIdx.x;
    const int h  = blockIdx.y;
    const int hk = h >> 2;
    const int tid  = threadIdx.x;
    const int warp = tid >> 5;
    const int lane = tid & 31;
    const int gid  = lane >> 2;
    const int tig  = lane & 3;
    const int q0 = warp * 16;

    const int a_r = lane & 15, a_c = (lane >> 4) << 3;
    const int b_r = ((lane >> 4) << 3) + (lane & 7), b_c = ((lane >> 3) & 1) * 8;

    const int hasret = (t >= 1) ? 1 : 0;
    const int ntiles = (t + 1) + hasret;
    const int rb = ((t < 16) ? t : 16) - 1;

    const __half* kbase = kc + (size_t)hk * KVTOT * HDIM;
    const __half* vbase = vt + (size_t)hk * HDIM * KVTOT;

    auto tokbase_of = [&](int it) {
        return (hasret && it == 0) ? rb * 64 : RLEN + (it - hasret) * 64;
    };
    auto issue_kv = [&](int it, int s) {
        const int tb2 = tokbase_of(it);
        const unsigned koff = sm_u + (AT_HW + s * 2 * AT_HW) * 2;
        const unsigned voff = koff + AT_HW * 2;
#pragma unroll
        for (int j = 0; j < 4; j++) {
            int id = tid + j * 128;
            int r = id >> 3, c8 = (id & 7) * 8;
            CP16(koff + (r * AT_STR + c8) * 2, &kbase[(size_t)(tb2 + r) * HDIM + c8]);
            CP16(voff + (r * AT_STR + c8) * 2, &vbase[(size_t)r * KVTOT + tb2 + c8]);
        }
    };

#pragma unroll
    for (int j = 0; j < 4; j++) {
        int id = tid + j * 128;
        int r = id >> 3, c8 = (id & 7) * 8;
        CP16(sm_u + (r * AT_STR + c8) * 2,
             &qh[(size_t)(t * 64 + r) * (NHEAD * HDIM) + h * HDIM + c8]);
    }
    issue_kv(0, 0);
    CP_COMMIT();

    unsigned qa[4][4];
    float m_lo = -1e30f, m_hi = -1e30f, l_lo = 0.f, l_hi = 0.f;
    float O[8][4];
#pragma unroll
    for (int nt = 0; nt < 8; nt++)
#pragma unroll
        for (int j = 0; j < 4; j++) O[nt][j] = 0.f;

    for (int it = 0; it < ntiles; it++) {
        const int s = it & 1;
        const bool isret = hasret && (it == 0);
        const int jt = it - hasret;

        if (it + 1 < ntiles) { issue_kv(it + 1, s ^ 1); CP_COMMIT(); CP_WAIT1(); }
        else                 { CP_WAIT0(); }
        __syncthreads();

        if (it == 0) {
#pragma unroll
            for (int kt = 0; kt < 4; kt++)
                ldsm_x4(qa[kt], sm_u + ((q0 + a_r) * AT_STR + kt * 16 + a_c) * 2);
        }

        const unsigned koff = sm_u + (AT_HW + s * 2 * AT_HW) * 2;
        const unsigned voff = koff + AT_HW * 2;

        float sacc[8][4];
#pragma unroll
        for (int nt = 0; nt < 8; nt++)
#pragma unroll
            for (int j = 0; j < 4; j++) sacc[nt][j] = 0.f;

#pragma unroll
        for (int kt = 0; kt < 4; kt++) {
            const int kb = kt * 16;
#pragma unroll
            for (int ng = 0; ng < 4; ng++) {
                unsigned b4[4];
                ldsm_x4(b4, koff + ((ng * 16 + b_r) * AT_STR + kb + b_c) * 2);
                mma16(sacc[ng * 2],     qa[kt], b4);
                mma16(sacc[ng * 2 + 1], qa[kt], b4 + 2);
            }
        }

        if (!isret) {
            const int s_lo = t * 64 + q0 + gid;
            const int s_hi = s_lo + 8;
#pragma unroll
            for (int nt = 0; nt < 8; nt++) {
#pragma unroll
                for (int j = 0; j < 2; j++) {
                    int n = jt * 64 + nt * 8 + 2 * tig + j;
                    bool inval = (n < 1);
                    if (inval || n > s_lo) sacc[nt][j]     = -1e30f;
                    if (inval || n > s_hi) sacc[nt][j + 2] = -1e30f;
                }
            }
        }

        float lm_lo = -1e30f, lm_hi = -1e30f;
#pragma unroll
        for (int nt = 0; nt < 8; nt++) {
            lm_lo = fmaxf(lm_lo, fmaxf(sacc[nt][0], sacc[nt][1]));
            lm_hi = fmaxf(lm_hi, fmaxf(sacc[nt][2], sacc[nt][3]));
        }
        lm_lo = fmaxf(lm_lo, __shfl_xor_sync(0xffffffffu, lm_lo, 1));
        lm_lo = fmaxf(lm_lo, __shfl_xor_sync(0xffffffffu, lm_lo, 2));
        lm_hi = fmaxf(lm_hi, __shfl_xor_sync(0xffffffffu, lm_hi, 1));
        lm_hi = fmaxf(lm_hi, __shfl_xor_sync(0xffffffffu, lm_hi, 2));
        const float mn_lo = fmaxf(m_lo, lm_lo);
        const float mn_hi = fmaxf(m_hi, lm_hi);

        float sum_lo = 0.f, sum_hi = 0.f;
#pragma unroll
        for (int nt = 0; nt < 8; nt++) {
            sacc[nt][0] = __expf(sacc[nt][0] - mn_lo);
            sacc[nt][1] = __expf(sacc[nt][1] - mn_lo);
            sacc[nt][2] = __expf(sacc[nt][2] - mn_hi);
            sacc[nt][3] = __expf(sacc[nt][3] - mn_hi);
            sum_lo += sacc[nt][0] + sacc[nt][1];
            sum_hi += sacc[nt][2] + sacc[nt][3];
        }
        sum_lo += __shfl_xor_sync(0xffffffffu, sum_lo, 1);
        sum_lo += __shfl_xor_sync(0xffffffffu, sum_lo, 2);
        sum_hi += __shfl_xor_sync(0xffffffffu, sum_hi, 1);
        sum_hi += __shfl_xor_sync(0xffffffffu, sum_hi, 2);

        const float f_lo = __expf(m_lo - mn_lo);
        const float f_hi = __expf(m_hi - mn_hi);
        m_lo = mn_lo; m_hi = mn_hi;
        l_lo = l_lo * f_lo + sum_lo;
        l_hi = l_hi * f_hi + sum_hi;
#pragma unroll
        for (int nt = 0; nt < 8; nt++) {
            O[nt][0] *= f_lo; O[nt][1] *= f_lo;
            O[nt][2] *= f_hi; O[nt][3] *= f_hi;
        }

#pragma unroll
        for (int kt = 0; kt < 4; kt++) {
            unsigned pa[4];
            pa[0] = packh2(sacc[2 * kt][0],     sacc[2 * kt][1]);
            pa[1] = packh2(sacc[2 * kt][2],     sacc[2 * kt][3]);
            pa[2] = packh2(sacc[2 * kt + 1][0], sacc[2 * kt + 1][1]);
            pa[3] = packh2(sacc[2 * kt + 1][2], sacc[2 * kt + 1][3]);
#pragma unroll
            for (int ng = 0; ng < 4; ng++) {
                unsigned b4[4];
                ldsm_x4(b4, voff + ((ng * 16 + b_r) * AT_STR + kt * 16 + b_c) * 2);
                mma16(O[ng * 2],     pa, b4);
                mma16(O[ng * 2 + 1], pa, b4 + 2);
            }
        }
        __syncthreads();
    }

    const float inv_lo = (m_lo > -1e29f) ? (1.f / l_lo) : 0.f;
    const float inv_hi = (m_hi > -1e29f) ? (1.f / l_hi) : 0.f;
#pragma unroll
    for (int nt = 0; nt < 8; nt++) {
        int col = nt * 8 + 2 * tig;
        size_t r_lo = (size_t)(t * 64 + q0 + gid)     * (NHEAD * HDIM) + h * HDIM + col;
        size_t r_hi = (size_t)(t * 64 + q0 + gid + 8) * (NHEAD * HDIM) + h * HDIM + col;
        *(unsigned*)&out[r_lo] = packh2(O[nt][0] * inv_lo, O[nt][1] * inv_lo);
        *(unsigned*)&out[r_hi] = packh2(O[nt][2] * inv_hi, O[nt][3] * inv_hi);
    }
}

// ---------------- launch ----------------
extern "C" void kernel_launch(void* const* d_in, const int* in_sizes, int n_in,
                              void* d_out, int out_size)
{
    const float* hidden = (const float*)d_in[0];
    const float* cosb   = (const float*)d_in[1];
    const float* sinb   = (const float*)d_in[2];
    const float* rk     = (const float*)d_in[3];
    const float* rv     = (const float*)d_in[4];
    const float* Wq     = (const float*)d_in[5];
    const float* Wk     = (const float*)d_in[6];
    const float* Wv     = (const float*)d_in[7];
    const float* Wo     = (const float*)d_in[8];
    float* out = (float*)d_out;

    __half *hth, *wqkv, *woh, *qh, *kc, *vn, *vtp, *ao;
    cudaGetSymbolAddress((void**)&hth,  g_hth);
    cudaGetSymbolAddress((void**)&wqkv, g_wqkv);
    cudaGetSymbolAddress((void**)&woh,  g_woh);
    cudaGetSymbolAddress((void**)&qh,   g_qh);
    cudaGetSymbolAddress((void**)&kc,   g_kc);
    cudaGetSymbolAddress((void**)&vn,   g_vn);
    cudaGetSymbolAddress((void**)&vtp,  g_vt);
    cudaGetSymbolAddress((void**)&ao,   g_ao);

    // 1. fp16 conversions
    conv_h<<<(SEQ * HID / 8 + 255) / 256, 256>>>((const float4*)hidden, (uint4*)hth, SEQ * HID / 8);
    conv_wcat<<<(HID * 512 + 255) / 256, 256>>>(Wq, wqkv, 2048, 0);
    conv_wcat<<<(HID * 128 + 255) / 256, 256>>>(Wk, wqkv, 512, 2048);
    conv_wcat<<<(HID * 128 + 255) / 256, 256>>>(Wv, wqkv, 512, 2560);
    conv_h<<<(HID * HID / 8 + 255) / 256, 256>>>((const float4*)Wo, (uint4*)woh, HID * HID / 8);

    // 2. fused QKV projection + rope epilogue
    cudaFuncSetAttribute(hgemm_qkv, cudaFuncAttributeMaxDynamicSharedMemorySize, SMEM_H);
    hgemm_qkv<<<dim3(NQKV / 128, SEQ / 128), 256, SMEM_H>>>(hth, wqkv, cosb, sinb, qh, kc, vn);

    // 3. retrieval K + V packing
    conv_rk<<<(NKVH * RLEN * (HDIM / 4) + 255) / 256, 256>>>(rk, kc);
    pack_v<<<dim3(KVTOT / 64, NKVH), 256>>>(vn, rv, vtp);

    // 4. attention
    cudaFuncSetAttribute(attn_tc, cudaFuncAttributeMaxDynamicSharedMemorySize, ATT_SMEM_BYTES);
    attn_tc<<<dim3(SEQ / 64, NHEAD), 128, ATT_SMEM_BYTES>>>(qh, kc, vtp, ao);

    // 5. output projection
    cudaFuncSetAttribute(hgemm_out, cudaFuncAttributeMaxDynamicSharedMemorySize, SMEM_H);
    hgemm_out<<<dim3(HID / 128, SEQ / 128), 256, SMEM_H>>>(ao, woh, out);
}

// round 10
// speedup vs baseline: 7.3515x; 1.0047x over previous
#include <cuda_runtime.h>
#include <cuda_fp16.h>
#include <cstdint>

// ---------------- problem constants ----------------
constexpr int SEQ  = 2048;
constexpr int HID  = 2048;
constexpr int NHEAD = 32;
constexpr int NKVH  = 8;
constexpr int HDIM  = 64;
constexpr int RLEN  = 1024;
constexpr int KVTOT = RLEN + SEQ;   // 3072
constexpr int NQKV  = NHEAD * HDIM + 2 * NKVH * HDIM;  // 3072
constexpr float SCALE = 0.125f;

// ---------------- scratch (device globals; no allocs) ----------------
__device__ __half g_hth [SEQ * HID];            // hidden fp16
__device__ __half g_wqkv[HID * NQKV];           // Wq|Wk|Wv fp16 [k][n]
__device__ __half g_woh [HID * HID];            // Wo fp16 [k][n]
__device__ __half g_qh  [SEQ * NHEAD * HDIM];   // roped+scaled Q fp16
__device__ __half g_kc  [NKVH * KVTOT * HDIM];  // unified K [hk][tok][d] fp16
__device__ __half g_vc  [NKVH * KVTOT * HDIM];  // unified V [hk][tok][d] fp16
__device__ __half g_ao  [SEQ * NHEAD * HDIM];   // attention out fp16

// ---------------- helpers ----------------
__device__ __forceinline__ unsigned packh2(float x, float y) {
    __half2 h = __floats2half2_rn(x, y);
    return *(unsigned*)&h;
}
__device__ __forceinline__ void mma16(float* c, const unsigned* a, const unsigned* b) {
    asm volatile(
        "mma.sync.aligned.m16n8k16.row.col.f32.f16.f16.f32 "
        "{%0,%1,%2,%3},{%4,%5,%6,%7},{%8,%9},{%0,%1,%2,%3};"
        : "+f"(c[0]), "+f"(c[1]), "+f"(c[2]), "+f"(c[3])
        : "r"(a[0]), "r"(a[1]), "r"(a[2]), "r"(a[3]), "r"(b[0]), "r"(b[1]));
}
__device__ __forceinline__ void ldsm_x4(unsigned* r, unsigned addr) {
    asm volatile("ldmatrix.sync.aligned.m8n8.x4.shared.b16 {%0,%1,%2,%3}, [%4];"
        : "=r"(r[0]), "=r"(r[1]), "=r"(r[2]), "=r"(r[3]) : "r"(addr));
}
__device__ __forceinline__ void ldsm_x4_t(unsigned* r, unsigned addr) {
    asm volatile("ldmatrix.sync.aligned.m8n8.x4.trans.shared.b16 {%0,%1,%2,%3}, [%4];"
        : "=r"(r[0]), "=r"(r[1]), "=r"(r[2]), "=r"(r[3]) : "r"(addr));
}
#define CP16(dst, src) asm volatile("cp.async.cg.shared.global [%0], [%1], 16;" :: "r"(dst), "l"(src))
#define CP_COMMIT()    asm volatile("cp.async.commit_group;")
#define CP_WAIT0()     asm volatile("cp.async.wait_group 0;")
#define CP_WAIT1()     asm volatile("cp.async.wait_group 1;")

// ================= conversion kernels =================
__global__ void conv_h(const float4* __restrict__ in, uint4* __restrict__ out, int n8) {
    int i = blockIdx.x * blockDim.x + threadIdx.x;
    if (i >= n8) return;
    float4 a = in[2 * i], b = in[2 * i + 1];
    out[i] = make_uint4(packh2(a.x, a.y), packh2(a.z, a.w),
                        packh2(b.x, b.y), packh2(b.z, b.w));
}
__global__ void conv_wcat(const float* __restrict__ W, __half* __restrict__ dst,
                          int ncols, int noff) {
    int id = blockIdx.x * blockDim.x + threadIdx.x;
    int n4c = ncols >> 2;
    if (id >= HID * n4c) return;
    int k = id / n4c, n4 = (id % n4c) * 4;
    float4 v = *(const float4*)&W[(size_t)k * ncols + n4];
    *(uint2*)&dst[(size_t)k * NQKV + noff + n4] = make_uint2(packh2(v.x, v.y), packh2(v.z, v.w));
}
// retrieval K or V fp32 [hk][1024][64] -> ret region of unified buffer [hk][tok][d]
__global__ void conv_ret(const float* __restrict__ src, __half* __restrict__ dst) {
    int id = blockIdx.x * blockDim.x + threadIdx.x;
    if (id >= NKVH * RLEN * (HDIM / 4)) return;
    int hk = id >> 14, rem = id & 16383;
    int r = rem >> 4, d4 = (rem & 15) * 4;
    float4 v = *(const float4*)&src[((size_t)hk * RLEN + r) * HDIM + d4];
    *(uint2*)&dst[(size_t)hk * KVTOT * HDIM + (size_t)r * HDIM + d4] =
        make_uint2(packh2(v.x, v.y), packh2(v.z, v.w));
}

// ================= fp16 GEMM mainloop: 3-stage cp.async, BM=128 BN=128 BK=32 =================
constexpr int GA_STR = 40;             // halfwords
constexpr int GB_STR = 136;
constexpr int GA_HW  = 128 * GA_STR;   // per stage
constexpr int GB_HW  = 32 * GB_STR;
constexpr int SMEM_H = 3 * (GA_HW + GB_HW) * 2;   // 56832 B

__device__ __forceinline__ void hgemm_main(
    const __half* __restrict__ A, const __half* __restrict__ B,
    int K, int N, int bm, int bn, int tid,
    unsigned as_u, unsigned bs_u, float acc[2][8][4])
{
    const int warp = tid >> 5;
    const int lane = tid & 31;
    const int m_base = (warp >> 1) * 32;
    const int n_base = (warp & 1) * 64;

    const int aRow = tid >> 2, aC = (tid & 3) * 8;
    const int bK   = tid >> 4, bN = (tid & 15) * 8;

    const int a_r = lane & 15, a_c = (lane >> 4) << 3;
    const int b_k = ((lane >> 3) & 1) * 8 + (lane & 7), b_n = (lane >> 4) << 3;

    auto issue = [&](int it, int s) {
        const size_t k0 = (size_t)it * 32;
        unsigned ad = as_u + (s * GA_HW + aRow * GA_STR + aC) * 2;
        CP16(ad,                   &A[(size_t)(bm + aRow) * K + k0 + aC]);
        CP16(ad + 64 * GA_STR * 2, &A[(size_t)(bm + aRow + 64) * K + k0 + aC]);
        unsigned bd = bs_u + (s * GB_HW + bK * GB_STR + bN) * 2;
        CP16(bd,                   &B[(k0 + bK) * N + bn + bN]);
        CP16(bd + 16 * GB_STR * 2, &B[(k0 + bK + 16) * N + bn + bN]);
    };

#pragma unroll
    for (int mt = 0; mt < 2; mt++)
#pragma unroll
        for (int nt = 0; nt < 8; nt++)
#pragma unroll
            for (int j = 0; j < 4; j++) acc[mt][nt][j] = 0.f;

    const int niter = K >> 5;
    issue(0, 0); CP_COMMIT();
    issue(1, 1); CP_COMMIT();

    for (int it = 0; it < niter; it++) {
        const int s = it % 3;
        CP_WAIT1();
        __syncthreads();

#pragma unroll
        for (int ks = 0; ks < 2; ks++) {
            const int kb = ks * 16;
            unsigned a[2][4];
#pragma unroll
            for (int mt = 0; mt < 2; mt++)
                ldsm_x4(a[mt], as_u + (s * GA_HW + (m_base + mt * 16 + a_r) * GA_STR + kb + a_c) * 2);
#pragma unroll
            for (int ng = 0; ng < 4; ng++) {
                unsigned b4[4];
                ldsm_x4_t(b4, bs_u + (s * GB_HW + (kb + b_k) * GB_STR + n_base + ng * 16 + b_n) * 2);
                mma16(acc[0][ng * 2],     a[0], b4);
                mma16(acc[0][ng * 2 + 1], a[0], b4 + 2);
                mma16(acc[1][ng * 2],     a[1], b4);
                mma16(acc[1][ng * 2 + 1], a[1], b4 + 2);
            }
        }
        if (it + 2 < niter) issue(it + 2, (it + 2) % 3);
        CP_COMMIT();
    }
}

// ---- fused QKV GEMM: epilogue applies rope + fp16 pack, scatters to qh/kc/vc ----
__global__ __launch_bounds__(256)
void hgemm_qkv(const __half* __restrict__ A, const __half* __restrict__ B,
               const float* __restrict__ cosb, const float* __restrict__ sinb,
               __half* __restrict__ qh, __half* __restrict__ kc, __half* __restrict__ vc)
{
    extern __shared__ __half smh[];
    const unsigned as_u = (unsigned)__cvta_generic_to_shared(smh);
    const unsigned bs_u = as_u + 3 * GA_HW * 2;
    const int tid = threadIdx.x;
    const int bm = blockIdx.y * 128, bn = blockIdx.x * 128;

    float acc[2][8][4];
    hgemm_main(A, B, HID, NQKV, bm, bn, tid, as_u, bs_u, acc);

    const int warp = tid >> 5, lane = tid & 31;
    const int gid = lane >> 2, tig = lane & 3;
    const int m_base = (warp >> 1) * 32;
    const int n_warp0 = bn + (warp & 1) * 64;   // 64-aligned: one head, one region

    if (n_warp0 < 2560) {
        // q or k: rope pairs (i, i+32) are (nt, nt+4) in-thread
        const float sc = (n_warp0 < 2048) ? SCALE : 1.f;
#pragma unroll
        for (int mt = 0; mt < 2; mt++) {
#pragma unroll
            for (int half = 0; half < 2; half++) {
                const int row = bm + m_base + mt * 16 + gid + half * 8;   // token
                const int jo = half * 2;
#pragma unroll
                for (int nt = 0; nt < 4; nt++) {
                    const int i = nt * 8 + 2 * tig;
                    float2 cc = *(const float2*)&cosb[(size_t)row * 64 + i];
                    float2 ss = *(const float2*)&sinb[(size_t)row * 64 + i];
                    float x00 = acc[mt][nt][jo],     x01 = acc[mt][nt][jo + 1];
                    float x10 = acc[mt][nt + 4][jo], x11 = acc[mt][nt + 4][jo + 1];
                    unsigned lo = packh2((x00 * cc.x - x10 * ss.x) * sc,
                                         (x01 * cc.y - x11 * ss.y) * sc);
                    unsigned hi = packh2((x10 * cc.x + x00 * ss.x) * sc,
                                         (x11 * cc.y + x01 * ss.y) * sc);
                    __half* d0;
                    if (n_warp0 < 2048) {
                        d0 = qh + (size_t)row * 2048 + n_warp0 + i;
                    } else {
                        const int rel = n_warp0 - 2048 + i;
                        d0 = kc + ((size_t)(rel >> 6) * KVTOT + RLEN + row) * HDIM + (rel & 63);
                    }
                    *(unsigned*)d0        = lo;
                    *(unsigned*)(d0 + 32) = hi;
                }
            }
        }
    } else {
        // v region: fp16 store straight into unified vc[hk][RLEN+tok][d]
#pragma unroll
        for (int mt = 0; mt < 2; mt++) {
#pragma unroll
            for (int half = 0; half < 2; half++) {
                const int row = bm + m_base + mt * 16 + gid + half * 8;
                const int jo = half * 2;
#pragma unroll
                for (int nt = 0; nt < 8; nt++) {
                    const int rel = n_warp0 + nt * 8 + 2 * tig - 2560;
                    __half* d0 = vc + ((size_t)(rel >> 6) * KVTOT + RLEN + row) * HDIM + (rel & 63);
                    *(unsigned*)d0 = packh2(acc[mt][nt][jo], acc[mt][nt][jo + 1]);
                }
            }
        }
    }
}

// ---- Wo GEMM: fp32 out ----
__global__ __launch_bounds__(256)
void hgemm_out(const __half* __restrict__ A, const __half* __restrict__ B,
               float* __restrict__ C)
{
    extern __shared__ __half smh[];
    const unsigned as_u = (unsigned)__cvta_generic_to_shared(smh);
    const unsigned bs_u = as_u + 3 * GA_HW * 2;
    const int tid = threadIdx.x;
    const int bm = blockIdx.y * 128, bn = blockIdx.x * 128;

    float acc[2][8][4];
    hgemm_main(A, B, HID, HID, bm, bn, tid, as_u, bs_u, acc);

    const int warp = tid >> 5, lane = tid & 31;
    const int gid = lane >> 2, tig = lane & 3;
    const int m_base = (warp >> 1) * 32;
    const int n_base = (warp & 1) * 64;
#pragma unroll
    for (int mt = 0; mt < 2; mt++)
#pragma unroll
        for (int nt = 0; nt < 8; nt++) {
            int row = bm + m_base + mt * 16 + gid;
            int col = bn + n_base + nt * 8 + 2 * tig;
            *(float2*)&C[(size_t)row * HID + col]       = make_float2(acc[mt][nt][0], acc[mt][nt][1]);
            *(float2*)&C[(size_t)(row + 8) * HID + col] = make_float2(acc[mt][nt][2], acc[mt][nt][3]);
        }
}

// ================= fp16 flash attention: 2 GQA heads per CTA share K/V =================
// 256 thr = 8 warps. Warps 0-3: head h0, warps 4-7: head h1 (same kv head).
// smem tiles (AT_HW halfwords each): Q0, Q1, then stage s in {0,1}: K, V.
constexpr int AT_STR = 72;
constexpr int AT_HW  = 64 * AT_STR;
constexpr int ATT_SMEM_BYTES = (AT_HW * 6) * 2;  // 55296 B

__global__ __launch_bounds__(256)
void attn_tc(const __half* __restrict__ qh, const __half* __restrict__ kc,
             const __half* __restrict__ vc, __half* __restrict__ out)
{
    extern __shared__ __half sm[];
    const unsigned sm_u = (unsigned)__cvta_generic_to_shared(sm);

    const int t    = (int)gridDim.x - 1 - (int)blockIdx.x;
    const int hk   = blockIdx.y >> 1;
    const int pair = blockIdx.y & 1;
    const int tid  = threadIdx.x;
    const int warp = tid >> 5;
    const int lane = tid & 31;
    const int gid  = lane >> 2;
    const int tig  = lane & 3;
    const int hd   = warp >> 2;            // which of the 2 heads
    const int h    = hk * 4 + pair * 2 + hd;
    const int q0   = (warp & 3) * 16;

    // fragment lane addressing
    const int a_r = lane & 15, a_c = (lane >> 4) << 3;                              // A frag
    const int b_r = ((lane >> 4) << 3) + (lane & 7), b_c = ((lane >> 3) & 1) * 8;   // B frag (K, non-trans)
    const int v_k = ((lane >> 3) & 1) * 8 + (lane & 7), v_n = (lane >> 4) << 3;     // B frag (V, trans)

    const int hasret = (t >= 1) ? 1 : 0;
    const int ntiles = (t + 1) + hasret;
    const int rb = ((t < 16) ? t : 16) - 1;

    const __half* kbase = kc + (size_t)hk * KVTOT * HDIM;
    const __half* vbase = vc + (size_t)hk * KVTOT * HDIM;

    auto tokbase_of = [&](int it) {
        return (hasret && it == 0) ? rb * 64 : RLEN + (it - hasret) * 64;
    };
    auto issue_kv = [&](int it, int s) {
        const int tb2 = tokbase_of(it);
        const unsigned koff = sm_u + (2 + 2 * s) * AT_HW * 2;
        const unsigned voff = koff + AT_HW * 2;
#pragma unroll
        for (int j = 0; j < 2; j++) {
            int id = tid + j * 256;
            int r = id >> 3, c8 = (id & 7) * 8;
            CP16(koff + (r * AT_STR + c8) * 2, &kbase[(size_t)(tb2 + r) * HDIM + c8]);
            CP16(voff + (r * AT_STR + c8) * 2, &vbase[(size_t)(tb2 + r) * HDIM + c8]);
        }
    };

    // prologue: both heads' Q + KV(0)
#pragma unroll
    for (int j = 0; j < 4; j++) {
        int id = tid + j * 256;
        int hq = id >> 9;                  // 512 cp16 per head tile
        int rem = id & 511;
        int r = rem >> 3, c8 = (rem & 7) * 8;
        CP16(sm_u + (hq * AT_HW + r * AT_STR + c8) * 2,
             &qh[(size_t)(t * 64 + r) * (NHEAD * HDIM) + (hk * 4 + pair * 2 + hq) * HDIM + c8]);
    }
    issue_kv(0, 0);
    CP_COMMIT();

    unsigned qa[4][4];
    float m_lo = -1e30f, m_hi = -1e30f, l_lo = 0.f, l_hi = 0.f;
    float O[8][4];
#pragma unroll
    for (int nt = 0; nt < 8; nt++)
#pragma unroll
        for (int j = 0; j < 4; j++) O[nt][j] = 0.f;

    for (int it = 0; it < ntiles; it++) {
        const int s = it & 1;
        const bool isret = hasret && (it == 0);
        const int jt = it - hasret;

        if (it + 1 < ntiles) { issue_kv(it + 1, s ^ 1); CP_COMMIT(); CP_WAIT1(); }
        else                 { CP_WAIT0(); }
        __syncthreads();

        if (it == 0) {
#pragma unroll
            for (int kt = 0; kt < 4; kt++)
                ldsm_x4(qa[kt], sm_u + (hd * AT_HW + (q0 + a_r) * AT_STR + kt * 16 + a_c) * 2);
        }

        const unsigned koff = sm_u + (2 + 2 * s) * AT_HW * 2;
        const unsigned voff = koff + AT_HW * 2;

        // S = Q K^T
        float sacc[8][4];
#pragma unroll
        for (int nt = 0; nt < 8; nt++)
#pragma unroll
            for (int j = 0; j < 4; j++) sacc[nt][j] = 0.f;

#pragma unroll
        for (int kt = 0; kt < 4; kt++) {
            const int kb = kt * 16;
#pragma unroll
            for (int ng = 0; ng < 4; ng++) {
                unsigned b4[4];
                ldsm_x4(b4, koff + ((ng * 16 + b_r) * AT_STR + kb + b_c) * 2);
                mma16(sacc[ng * 2],     qa[kt], b4);
                mma16(sacc[ng * 2 + 1], qa[kt], b4 + 2);
            }
        }

        // mask (new-token tiles only; retrieval block fully valid)
        if (!isret) {
            const int s_lo = t * 64 + q0 + gid;
            const int s_hi = s_lo + 8;
#pragma unroll
            for (int nt = 0; nt < 8; nt++) {
#pragma unroll
                for (int j = 0; j < 2; j++) {
                    int n = jt * 64 + nt * 8 + 2 * tig + j;
                    bool inval = (n < 1);
                    if (inval || n > s_lo) sacc[nt][j]     = -1e30f;
                    if (inval || n > s_hi) sacc[nt][j + 2] = -1e30f;
                }
            }
        }

        // online softmax
        float lm_lo = -1e30f, lm_hi = -1e30f;
#pragma unroll
        for (int nt = 0; nt < 8; nt++) {
            lm_lo = fmaxf(lm_lo, fmaxf(sacc[nt][0], sacc[nt][1]));
            lm_hi = fmaxf(lm_hi, fmaxf(sacc[nt][2], sacc[nt][3]));
        }
        lm_lo = fmaxf(lm_lo, __shfl_xor_sync(0xffffffffu, lm_lo, 1));
        lm_lo = fmaxf(lm_lo, __shfl_xor_sync(0xffffffffu, lm_lo, 2));
        lm_hi = fmaxf(lm_hi, __shfl_xor_sync(0xffffffffu, lm_hi, 1));
        lm_hi = fmaxf(lm_hi, __shfl_xor_sync(0xffffffffu, lm_hi, 2));
        const float mn_lo = fmaxf(m_lo, lm_lo);
        const float mn_hi = fmaxf(m_hi, lm_hi);

        float sum_lo = 0.f, sum_hi = 0.f;
#pragma unroll
        for (int nt = 0; nt < 8; nt++) {
            sacc[nt][0] = __expf(sacc[nt][0] - mn_lo);
            sacc[nt][1] = __expf(sacc[nt][1] - mn_lo);
            sacc[nt][2] = __expf(sacc[nt][2] - mn_hi);
            sacc[nt][3] = __expf(sacc[nt][3] - mn_hi);
            sum_lo += sacc[nt][0] + sacc[nt][1];
            sum_hi += sacc[nt][2] + sacc[nt][3];
        }
        sum_lo += __shfl_xor_sync(0xffffffffu, sum_lo, 1);
        sum_lo += __shfl_xor_sync(0xffffffffu, sum_lo, 2);
        sum_hi += __shfl_xor_sync(0xffffffffu, sum_hi, 1);
        sum_hi += __shfl_xor_sync(0xffffffffu, sum_hi, 2);

        const float f_lo = __expf(m_lo - mn_lo);
        const float f_hi = __expf(m_hi - mn_hi);
        m_lo = mn_lo; m_hi = mn_hi;
        l_lo = l_lo * f_lo + sum_lo;
        l_hi = l_hi * f_hi + sum_hi;
#pragma unroll
        for (int nt = 0; nt < 8; nt++) {
            O[nt][0] *= f_lo; O[nt][1] *= f_lo;
            O[nt][2] *= f_hi; O[nt][3] *= f_hi;
        }

        // O += P @ V  (V [tok][d] via trans ldmatrix)
#pragma unroll
        for (int kt = 0; kt < 4; kt++) {
            unsigned pa[4];
            pa[0] = packh2(sacc[2 * kt][0],     sacc[2 * kt][1]);
            pa[1] = packh2(sacc[2 * kt][2],     sacc[2 * kt][3]);
            pa[2] = packh2(sacc[2 * kt + 1][0], sacc[2 * kt + 1][1]);
            pa[3] = packh2(sacc[2 * kt + 1][2], sacc[2 * kt + 1][3]);
#pragma unroll
            for (int ng = 0; ng < 4; ng++) {
                unsigned b4[4];
                ldsm_x4_t(b4, voff + ((kt * 16 + v_k) * AT_STR + ng * 16 + v_n) * 2);
                mma16(O[ng * 2],     pa, b4);
                mma16(O[ng * 2 + 1], pa, b4 + 2);
            }
        }
        __syncthreads();   // stage reuse guard
    }

    // epilogue
    const float inv_lo = (m_lo > -1e29f) ? (1.f / l_lo) : 0.f;
    const float inv_hi = (m_hi > -1e29f) ? (1.f / l_hi) : 0.f;
#pragma unroll
    for (int nt = 0; nt < 8; nt++) {
        int col = nt * 8 + 2 * tig;
        size_t r_lo = (size_t)(t * 64 + q0 + gid)     * (NHEAD * HDIM) + h * HDIM + col;
        size_t r_hi = (size_t)(t * 64 + q0 + gid + 8) * (NHEAD * HDIM) + h * HDIM + col;
        *(unsigned*)&out[r_lo] = packh2(O[nt][0] * inv_lo, O[nt][1] * inv_lo);
        *(unsigned*)&out[r_hi] = packh2(O[nt][2] * inv_hi, O[nt][3] * inv_hi);
    }
}

// ---------------- launch ----------------
extern "C" void kernel_launch(void* const* d_in, const int* in_sizes, int n_in,
                              void* d_out, int out_size)
{
    const float* hidden = (const float*)d_in[0];
    const float* cosb   = (const float*)d_in[1];
    const float* sinb   = (const float*)d_in[2];
    const float* rk     = (const float*)d_in[3];
    const float* rv     = (const float*)d_in[4];
    const float* Wq     = (const float*)d_in[5];
    const float* Wk     = (const float*)d_in[6];
    const float* Wv     = (const float*)d_in[7];
    const float* Wo     = (const float*)d_in[8];
    float* out = (float*)d_out;

    __half *hth, *wqkv, *woh, *qh, *kc, *vc, *ao;
    cudaGetSymbolAddress((void**)&hth,  g_hth);
    cudaGetSymbolAddress((void**)&wqkv, g_wqkv);
    cudaGetSymbolAddress((void**)&woh,  g_woh);
    cudaGetSymbolAddress((void**)&qh,   g_qh);
    cudaGetSymbolAddress((void**)&kc,   g_kc);
    cudaGetSymbolAddress((void**)&vc,   g_vc);
    cudaGetSymbolAddress((void**)&ao,   g_ao);

    // 1. fp16 conversions
    conv_h<<<(SEQ * HID / 8 + 255) / 256, 256>>>((const float4*)hidden, (uint4*)hth, SEQ * HID / 8);
    conv_wcat<<<(HID * 512 + 255) / 256, 256>>>(Wq, wqkv, 2048, 0);
    conv_wcat<<<(HID * 128 + 255) / 256, 256>>>(Wk, wqkv, 512, 2048);
    conv_wcat<<<(HID * 128 + 255) / 256, 256>>>(Wv, wqkv, 512, 2560);
    conv_h<<<(HID * HID / 8 + 255) / 256, 256>>>((const float4*)Wo, (uint4*)woh, HID * HID / 8);

    // 2. fused QKV projection + rope epilogue (writes qh/kc/vc directly)
    cudaFuncSetAttribute(hgemm_qkv, cudaFuncAttributeMaxDynamicSharedMemorySize, SMEM_H);
    hgemm_qkv<<<dim3(NQKV / 128, SEQ / 128), 256, SMEM_H>>>(hth, wqkv, cosb, sinb, qh, kc, vc);

    // 3. retrieval K/V into unified buffers
    conv_ret<<<(NKVH * RLEN * (HDIM / 4) + 255) / 256, 256>>>(rk, kc);
    conv_ret<<<(NKVH * RLEN * (HDIM / 4) + 255) / 256, 256>>>(rv, vc);

    // 4. attention (2 GQA heads per CTA)
    cudaFuncSetAttribute(attn_tc, cudaFuncAttributeMaxDynamicSharedMemorySize, ATT_SMEM_BYTES);
    attn_tc<<<dim3(SEQ / 64, NHEAD / 2), 256, ATT_SMEM_BYTES>>>(qh, kc, vc, ao);

    // 5. output projection
    cudaFuncSetAttribute(hgemm_out, cudaFuncAttributeMaxDynamicSharedMemorySize, SMEM_H);
    hgemm_out<<<dim3(HID / 128, SEQ / 128), 256, SMEM_H>>>(ao, woh, out);
}

// round 11
// speedup vs baseline: 7.8753x; 1.0712x over previous
#include <cuda_runtime.h>
#include <cuda_fp16.h>
#include <cstdint>

// ---------------- problem constants ----------------
constexpr int SEQ  = 2048;
constexpr int HID  = 2048;
constexpr int NHEAD = 32;
constexpr int NKVH  = 8;
constexpr int HDIM  = 64;
constexpr int RLEN  = 1024;
constexpr int KVTOT = RLEN + SEQ;   // 3072
constexpr int NQKV  = NHEAD * HDIM + 2 * NKVH * HDIM;  // 3072
constexpr float SCALE = 0.125f;
constexpr float LOG2E = 1.44269504088896340736f;

// ---------------- scratch (device globals; no allocs) ----------------
__device__ __half g_hth [SEQ * HID];            // hidden fp16
__device__ __half g_wqkv[HID * NQKV];           // Wq|Wk|Wv fp16 [k][n]
__device__ __half g_woh [HID * HID];            // Wo fp16 [k][n]
__device__ __half g_qh  [SEQ * NHEAD * HDIM];   // roped Q fp16, pre-scaled by SCALE*log2(e)
__device__ __half g_kc  [NKVH * KVTOT * HDIM];  // unified K [hk][tok][d] fp16
__device__ __half g_vc  [NKVH * KVTOT * HDIM];  // unified V [hk][tok][d] fp16
__device__ __half g_ao  [SEQ * NHEAD * HDIM];   // attention out fp16

// ---------------- helpers ----------------
__device__ __forceinline__ unsigned packh2(float x, float y) {
    __half2 h = __floats2half2_rn(x, y);
    return *(unsigned*)&h;
}
__device__ __forceinline__ float ex2(float x) {
    float r;
    asm("ex2.approx.f32 %0, %1;" : "=f"(r) : "f"(x));
    return r;
}
__device__ __forceinline__ void mma16(float* c, const unsigned* a, const unsigned* b) {
    asm volatile(
        "mma.sync.aligned.m16n8k16.row.col.f32.f16.f16.f32 "
        "{%0,%1,%2,%3},{%4,%5,%6,%7},{%8,%9},{%0,%1,%2,%3};"
        : "+f"(c[0]), "+f"(c[1]), "+f"(c[2]), "+f"(c[3])
        : "r"(a[0]), "r"(a[1]), "r"(a[2]), "r"(a[3]), "r"(b[0]), "r"(b[1]));
}
__device__ __forceinline__ void ldsm_x4(unsigned* r, unsigned addr) {
    asm volatile("ldmatrix.sync.aligned.m8n8.x4.shared.b16 {%0,%1,%2,%3}, [%4];"
        : "=r"(r[0]), "=r"(r[1]), "=r"(r[2]), "=r"(r[3]) : "r"(addr));
}
__device__ __forceinline__ void ldsm_x4_t(unsigned* r, unsigned addr) {
    asm volatile("ldmatrix.sync.aligned.m8n8.x4.trans.shared.b16 {%0,%1,%2,%3}, [%4];"
        : "=r"(r[0]), "=r"(r[1]), "=r"(r[2]), "=r"(r[3]) : "r"(addr));
}
#define CP16(dst, src) asm volatile("cp.async.cg.shared.global [%0], [%1], 16;" :: "r"(dst), "l"(src))
#define CP_COMMIT()    asm volatile("cp.async.commit_group;")
#define CP_WAIT0()     asm volatile("cp.async.wait_group 0;")
#define CP_WAIT1()     asm volatile("cp.async.wait_group 1;")

// ================= conversion kernels =================
__global__ void conv_h(const float4* __restrict__ in, uint4* __restrict__ out, int n8) {
    int i = blockIdx.x * blockDim.x + threadIdx.x;
    if (i >= n8) return;
    float4 a = in[2 * i], b = in[2 * i + 1];
    out[i] = make_uint4(packh2(a.x, a.y), packh2(a.z, a.w),
                        packh2(b.x, b.y), packh2(b.z, b.w));
}
__global__ void conv_wcat(const float* __restrict__ W, __half* __restrict__ dst,
                          int ncols, int noff) {
    int id = blockIdx.x * blockDim.x + threadIdx.x;
    int n4c = ncols >> 2;
    if (id >= HID * n4c) return;
    int k = id / n4c, n4 = (id % n4c) * 4;
    float4 v = *(const float4*)&W[(size_t)k * ncols + n4];
    *(uint2*)&dst[(size_t)k * NQKV + noff + n4] = make_uint2(packh2(v.x, v.y), packh2(v.z, v.w));
}
// retrieval K or V fp32 [hk][1024][64] -> ret region of unified buffer [hk][tok][d]
__global__ void conv_ret(const float* __restrict__ src, __half* __restrict__ dst) {
    int id = blockIdx.x * blockDim.x + threadIdx.x;
    if (id >= NKVH * RLEN * (HDIM / 4)) return;
    int hk = id >> 14, rem = id & 16383;
    int r = rem >> 4, d4 = (rem & 15) * 4;
    float4 v = *(const float4*)&src[((size_t)hk * RLEN + r) * HDIM + d4];
    *(uint2*)&dst[(size_t)hk * KVTOT * HDIM + (size_t)r * HDIM + d4] =
        make_uint2(packh2(v.x, v.y), packh2(v.z, v.w));
}

// ================= fp16 GEMM mainloop: 3-stage cp.async, BM=128 BN=128 BK=32 =================
constexpr int GA_STR = 40;             // halfwords
constexpr int GB_STR = 136;
constexpr int GA_HW  = 128 * GA_STR;   // per stage
constexpr int GB_HW  = 32 * GB_STR;
constexpr int SMEM_H = 3 * (GA_HW + GB_HW) * 2;   // 56832 B

__device__ __forceinline__ void hgemm_main(
    const __half* __restrict__ A, const __half* __restrict__ B,
    int K, int N, int bm, int bn, int tid,
    unsigned as_u, unsigned bs_u, float acc[2][8][4])
{
    const int warp = tid >> 5;
    const int lane = tid & 31;
    const int m_base = (warp >> 1) * 32;
    const int n_base = (warp & 1) * 64;

    const int aRow = tid >> 2, aC = (tid & 3) * 8;
    const int bK   = tid >> 4, bN = (tid & 15) * 8;

    const int a_r = lane & 15, a_c = (lane >> 4) << 3;
    const int b_k = ((lane >> 3) & 1) * 8 + (lane & 7), b_n = (lane >> 4) << 3;

    auto issue = [&](int it, int s) {
        const size_t k0 = (size_t)it * 32;
        unsigned ad = as_u + (s * GA_HW + aRow * GA_STR + aC) * 2;
        CP16(ad,                   &A[(size_t)(bm + aRow) * K + k0 + aC]);
        CP16(ad + 64 * GA_STR * 2, &A[(size_t)(bm + aRow + 64) * K + k0 + aC]);
        unsigned bd = bs_u + (s * GB_HW + bK * GB_STR + bN) * 2;
        CP16(bd,                   &B[(k0 + bK) * N + bn + bN]);
        CP16(bd + 16 * GB_STR * 2, &B[(k0 + bK + 16) * N + bn + bN]);
    };

#pragma unroll
    for (int mt = 0; mt < 2; mt++)
#pragma unroll
        for (int nt = 0; nt < 8; nt++)
#pragma unroll
            for (int j = 0; j < 4; j++) acc[mt][nt][j] = 0.f;

    const int niter = K >> 5;
    issue(0, 0); CP_COMMIT();
    issue(1, 1); CP_COMMIT();

    for (int it = 0; it < niter; it++) {
        const int s = it % 3;
        CP_WAIT1();
        __syncthreads();

#pragma unroll
        for (int ks = 0; ks < 2; ks++) {
            const int kb = ks * 16;
            unsigned a[2][4];
#pragma unroll
            for (int mt = 0; mt < 2; mt++)
                ldsm_x4(a[mt], as_u + (s * GA_HW + (m_base + mt * 16 + a_r) * GA_STR + kb + a_c) * 2);
#pragma unroll
            for (int ng = 0; ng < 4; ng++) {
                unsigned b4[4];
                ldsm_x4_t(b4, bs_u + (s * GB_HW + (kb + b_k) * GB_STR + n_base + ng * 16 + b_n) * 2);
                mma16(acc[0][ng * 2],     a[0], b4);
                mma16(acc[0][ng * 2 + 1], a[0], b4 + 2);
                mma16(acc[1][ng * 2],     a[1], b4);
                mma16(acc[1][ng * 2 + 1], a[1], b4 + 2);
            }
        }
        if (it + 2 < niter) issue(it + 2, (it + 2) % 3);
        CP_COMMIT();
    }
}

// ---- fused QKV GEMM: epilogue applies rope + fp16 pack, scatters to qh/kc/vc ----
__global__ __launch_bounds__(256)
void hgemm_qkv(const __half* __restrict__ A, const __half* __restrict__ B,
               const float* __restrict__ cosb, const float* __restrict__ sinb,
               __half* __restrict__ qh, __half* __restrict__ kc, __half* __restrict__ vc)
{
    extern __shared__ __half smh[];
    const unsigned as_u = (unsigned)__cvta_generic_to_shared(smh);
    const unsigned bs_u = as_u + 3 * GA_HW * 2;
    const int tid = threadIdx.x;
    const int bm = blockIdx.y * 128, bn = blockIdx.x * 128;

    float acc[2][8][4];
    hgemm_main(A, B, HID, NQKV, bm, bn, tid, as_u, bs_u, acc);

    const int warp = tid >> 5, lane = tid & 31;
    const int gid = lane >> 2, tig = lane & 3;
    const int m_base = (warp >> 1) * 32;
    const int n_warp0 = bn + (warp & 1) * 64;   // 64-aligned: one head, one region

    if (n_warp0 < 2560) {
        // q or k: rope pairs (i, i+32) are (nt, nt+4) in-thread
        // q additionally pre-scaled by SCALE*log2(e) for the exp2 softmax
        const float sc = (n_warp0 < 2048) ? SCALE * LOG2E : 1.f;
#pragma unroll
        for (int mt = 0; mt < 2; mt++) {
#pragma unroll
            for (int half = 0; half < 2; half++) {
                const int row = bm + m_base + mt * 16 + gid + half * 8;   // token
                const int jo = half * 2;
#pragma unroll
                for (int nt = 0; nt < 4; nt++) {
                    const int i = nt * 8 + 2 * tig;
                    float2 cc = *(const float2*)&cosb[(size_t)row * 64 + i];
                    float2 ss = *(const float2*)&sinb[(size_t)row * 64 + i];
                    float x00 = acc[mt][nt][jo],     x01 = acc[mt][nt][jo + 1];
                    float x10 = acc[mt][nt + 4][jo], x11 = acc[mt][nt + 4][jo + 1];
                    unsigned lo = packh2((x00 * cc.x - x10 * ss.x) * sc,
                                         (x01 * cc.y - x11 * ss.y) * sc);
                    unsigned hi = packh2((x10 * cc.x + x00 * ss.x) * sc,
                                         (x11 * cc.y + x01 * ss.y) * sc);
                    __half* d0;
                    if (n_warp0 < 2048) {
                        d0 = qh + (size_t)row * 2048 + n_warp0 + i;
                    } else {
                        const int rel = n_warp0 - 2048 + i;
                        d0 = kc + ((size_t)(rel >> 6) * KVTOT + RLEN + row) * HDIM + (rel & 63);
                    }
                    *(unsigned*)d0        = lo;
                    *(unsigned*)(d0 + 32) = hi;
                }
            }
        }
    } else {
        // v region: fp16 store straight into unified vc[hk][RLEN+tok][d]
#pragma unroll
        for (int mt = 0; mt < 2; mt++) {
#pragma unroll
            for (int half = 0; half < 2; half++) {
                const int row = bm + m_base + mt * 16 + gid + half * 8;
                const int jo = half * 2;
#pragma unroll
                for (int nt = 0; nt < 8; nt++) {
                    const int rel = n_warp0 + nt * 8 + 2 * tig - 2560;
                    __half* d0 = vc + ((size_t)(rel >> 6) * KVTOT + RLEN + row) * HDIM + (rel & 63);
                    *(unsigned*)d0 = packh2(acc[mt][nt][jo], acc[mt][nt][jo + 1]);
                }
            }
        }
    }
}

// ---- Wo GEMM: fp32 out ----
__global__ __launch_bounds__(256)
void hgemm_out(const __half* __restrict__ A, const __half* __restrict__ B,
               float* __restrict__ C)
{
    extern __shared__ __half smh[];
    const unsigned as_u = (unsigned)__cvta_generic_to_shared(smh);
    const unsigned bs_u = as_u + 3 * GA_HW * 2;
    const int tid = threadIdx.x;
    const int bm = blockIdx.y * 128, bn = blockIdx.x * 128;

    float acc[2][8][4];
    hgemm_main(A, B, HID, HID, bm, bn, tid, as_u, bs_u, acc);

    const int warp = tid >> 5, lane = tid & 31;
    const int gid = lane >> 2, tig = lane & 3;
    const int m_base = (warp >> 1) * 32;
    const int n_base = (warp & 1) * 64;
#pragma unroll
    for (int mt = 0; mt < 2; mt++)
#pragma unroll
        for (int nt = 0; nt < 8; nt++) {
            int row = bm + m_base + mt * 16 + gid;
            int col = bn + n_base + nt * 8 + 2 * tig;
            *(float2*)&C[(size_t)row * HID + col]       = make_float2(acc[mt][nt][0], acc[mt][nt][1]);
            *(float2*)&C[(size_t)(row + 8) * HID + col] = make_float2(acc[mt][nt][2], acc[mt][nt][3]);
        }
}

// ================= fp16 flash attention: balanced paired q-tiles =================
// 128 thr = 4 warps, 1 head per CTA. CTA bx processes q-tiles {16+bx, 15-bx}
// sequentially -> constant 35 tile-iters per CTA (perfect load balance).
// smem tiles (AT_HW halfwords each): Q, then stage s in {0,1}: K, V.
constexpr int AT_STR = 72;
constexpr int AT_HW  = 64 * AT_STR;
constexpr int ATT_SMEM_BYTES = (AT_HW * 5) * 2;  // 46080 B

__global__ __launch_bounds__(128)
void attn_tc(const __half* __restrict__ qh, const __half* __restrict__ kc,
             const __half* __restrict__ vc, __half* __restrict__ out)
{
    extern __shared__ __half sm[];
    const unsigned sm_u = (unsigned)__cvta_generic_to_shared(sm);

    const int bx   = blockIdx.x;           // 0..15 pair index
    const int h    = blockIdx.y;
    const int hk   = h >> 2;
    const int tid  = threadIdx.x;
    const int warp = tid >> 5;
    const int lane = tid & 31;
    const int gid  = lane >> 2;
    const int tig  = lane & 3;
    const int q0   = warp * 16;

    // fragment lane addressing
    const int a_r = lane & 15, a_c = (lane >> 4) << 3;                              // A frag
    const int b_r = ((lane >> 4) << 3) + (lane & 7), b_c = ((lane >> 3) & 1) * 8;   // B frag (K)
    const int v_k = ((lane >> 3) & 1) * 8 + (lane & 7), v_n = (lane >> 4) << 3;     // B frag (V, trans)

    const __half* kbase = kc + (size_t)hk * KVTOT * HDIM;
    const __half* vbase = vc + (size_t)hk * KVTOT * HDIM;

    for (int phase = 0; phase < 2; phase++) {
        const int t = phase ? (15 - bx) : (16 + bx);

        const int hasret = (t >= 1) ? 1 : 0;
        const int ntiles = (t + 1) + hasret;
        const int rb = ((t < 16) ? t : 16) - 1;

        auto tokbase_of = [&](int it) {
            return (hasret && it == 0) ? rb * 64 : RLEN + (it - hasret) * 64;
        };
        auto issue_kv = [&](int it, int s) {
            const int tb2 = tokbase_of(it);
            const unsigned koff = sm_u + (1 + 2 * s) * AT_HW * 2;
            const unsigned voff = koff + AT_HW * 2;
#pragma unroll
            for (int j = 0; j < 4; j++) {
                int id = tid + j * 128;
                int r = id >> 3, c8 = (id & 7) * 8;
                CP16(koff + (r * AT_STR + c8) * 2, &kbase[(size_t)(tb2 + r) * HDIM + c8]);
                CP16(voff + (r * AT_STR + c8) * 2, &vbase[(size_t)(tb2 + r) * HDIM + c8]);
            }
        };

        // prologue: Q + KV(0)
#pragma unroll
        for (int j = 0; j < 4; j++) {
            int id = tid + j * 128;
            int r = id >> 3, c8 = (id & 7) * 8;
            CP16(sm_u + (r * AT_STR + c8) * 2,
                 &qh[(size_t)(t * 64 + r) * (NHEAD * HDIM) + h * HDIM + c8]);
        }
        issue_kv(0, 0);
        CP_COMMIT();

        unsigned qa[4][4];
        float m_lo = -1e30f, m_hi = -1e30f, l_lo = 0.f, l_hi = 0.f;
        float O[8][4];
#pragma unroll
        for (int nt = 0; nt < 8; nt++)
#pragma unroll
            for (int j = 0; j < 4; j++) O[nt][j] = 0.f;

        for (int it = 0; it < ntiles; it++) {
            const int s = it & 1;
            const bool isret = hasret && (it == 0);
            const int jt = it - hasret;

            if (it + 1 < ntiles) { issue_kv(it + 1, s ^ 1); CP_COMMIT(); CP_WAIT1(); }
            else                 { CP_WAIT0(); }
            __syncthreads();

            if (it == 0) {
#pragma unroll
                for (int kt = 0; kt < 4; kt++)
                    ldsm_x4(qa[kt], sm_u + ((q0 + a_r) * AT_STR + kt * 16 + a_c) * 2);
            }

            const unsigned koff = sm_u + (1 + 2 * s) * AT_HW * 2;
            const unsigned voff = koff + AT_HW * 2;

            // S = Q K^T  (log2-domain logits: Q pre-scaled by SCALE*log2e)
            float sacc[8][4];
#pragma unroll
            for (int nt = 0; nt < 8; nt++)
#pragma unroll
                for (int j = 0; j < 4; j++) sacc[nt][j] = 0.f;

#pragma unroll
            for (int kt = 0; kt < 4; kt++) {
                const int kb = kt * 16;
#pragma unroll
                for (int ng = 0; ng < 4; ng++) {
                    unsigned b4[4];
                    ldsm_x4(b4, koff + ((ng * 16 + b_r) * AT_STR + kb + b_c) * 2);
                    mma16(sacc[ng * 2],     qa[kt], b4);
                    mma16(sacc[ng * 2 + 1], qa[kt], b4 + 2);
                }
            }

            // mask (new-token tiles only; retrieval block fully valid)
            if (!isret) {
                const int s_lo = t * 64 + q0 + gid;
                const int s_hi = s_lo + 8;
#pragma unroll
                for (int nt = 0; nt < 8; nt++) {
#pragma unroll
                    for (int j = 0; j < 2; j++) {
                        int n = jt * 64 + nt * 8 + 2 * tig + j;
                        bool inval = (n < 1);
                        if (inval || n > s_lo) sacc[nt][j]     = -1e30f;
                        if (inval || n > s_hi) sacc[nt][j + 2] = -1e30f;
                    }
                }
            }

            // online softmax (base-2)
            float lm_lo = -1e30f, lm_hi = -1e30f;
#pragma unroll
            for (int nt = 0; nt < 8; nt++) {
                lm_lo = fmaxf(lm_lo, fmaxf(sacc[nt][0], sacc[nt][1]));
                lm_hi = fmaxf(lm_hi, fmaxf(sacc[nt][2], sacc[nt][3]));
            }
            lm_lo = fmaxf(lm_lo, __shfl_xor_sync(0xffffffffu, lm_lo, 1));
            lm_lo = fmaxf(lm_lo, __shfl_xor_sync(0xffffffffu, lm_lo, 2));
            lm_hi = fmaxf(lm_hi, __shfl_xor_sync(0xffffffffu, lm_hi, 1));
            lm_hi = fmaxf(lm_hi, __shfl_xor_sync(0xffffffffu, lm_hi, 2));
            const float mn_lo = fmaxf(m_lo, lm_lo);
            const float mn_hi = fmaxf(m_hi, lm_hi);

            float sum_lo = 0.f, sum_hi = 0.f;
#pragma unroll
            for (int nt = 0; nt < 8; nt++) {
                sacc[nt][0] = ex2(sacc[nt][0] - mn_lo);
                sacc[nt][1] = ex2(sacc[nt][1] - mn_lo);
                sacc[nt][2] = ex2(sacc[nt][2] - mn_hi);
                sacc[nt][3] = ex2(sacc[nt][3] - mn_hi);
                sum_lo += sacc[nt][0] + sacc[nt][1];
                sum_hi += sacc[nt][2] + sacc[nt][3];
            }
            sum_lo += __shfl_xor_sync(0xffffffffu, sum_lo, 1);
            sum_lo += __shfl_xor_sync(0xffffffffu, sum_lo, 2);
            sum_hi += __shfl_xor_sync(0xffffffffu, sum_hi, 1);
            sum_hi += __shfl_xor_sync(0xffffffffu, sum_hi, 2);

            const float f_lo = ex2(m_lo - mn_lo);
            const float f_hi = ex2(m_hi - mn_hi);
            m_lo = mn_lo; m_hi = mn_hi;
            l_lo = l_lo * f_lo + sum_lo;
            l_hi = l_hi * f_hi + sum_hi;
#pragma unroll
            for (int nt = 0; nt < 8; nt++) {
                O[nt][0] *= f_lo; O[nt][1] *= f_lo;
                O[nt][2] *= f_hi; O[nt][3] *= f_hi;
            }

            // O += P @ V  (V [tok][d] via trans ldmatrix)
#pragma unroll
            for (int kt = 0; kt < 4; kt++) {
                unsigned pa[4];
                pa[0] = packh2(sacc[2 * kt][0],     sacc[2 * kt][1]);
                pa[1] = packh2(sacc[2 * kt][2],     sacc[2 * kt][3]);
                pa[2] = packh2(sacc[2 * kt + 1][0], sacc[2 * kt + 1][1]);
                pa[3] = packh2(sacc[2 * kt + 1][2], sacc[2 * kt + 1][3]);
#pragma unroll
                for (int ng = 0; ng < 4; ng++) {
                    unsigned b4[4];
                    ldsm_x4_t(b4, voff + ((kt * 16 + v_k) * AT_STR + ng * 16 + v_n) * 2);
                    mma16(O[ng * 2],     pa, b4);
                    mma16(O[ng * 2 + 1], pa, b4 + 2);
                }
            }
            __syncthreads();   // stage reuse guard
        }

        // epilogue for this q-tile
        const float inv_lo = (m_lo > -1e29f) ? (1.f / l_lo) : 0.f;
        const float inv_hi = (m_hi > -1e29f) ? (1.f / l_hi) : 0.f;
#pragma unroll
        for (int nt = 0; nt < 8; nt++) {
            int col = nt * 8 + 2 * tig;
            size_t r_lo = (size_t)(t * 64 + q0 + gid)     * (NHEAD * HDIM) + h * HDIM + col;
            size_t r_hi = (size_t)(t * 64 + q0 + gid + 8) * (NHEAD * HDIM) + h * HDIM + col;
            *(unsigned*)&out[r_lo] = packh2(O[nt][0] * inv_lo, O[nt][1] * inv_lo);
            *(unsigned*)&out[r_hi] = packh2(O[nt][2] * inv_hi, O[nt][3] * inv_hi);
        }
    }
}

// ---------------- launch ----------------
extern "C" void kernel_launch(void* const* d_in, const int* in_sizes, int n_in,
                              void* d_out, int out_size)
{
    const float* hidden = (const float*)d_in[0];
    const float* cosb   = (const float*)d_in[1];
    const float* sinb   = (const float*)d_in[2];
    const float* rk     = (const float*)d_in[3];
    const float* rv     = (const float*)d_in[4];
    const float* Wq     = (const float*)d_in[5];
    const float* Wk     = (const float*)d_in[6];
    const float* Wv     = (const float*)d_in[7];
    const float* Wo     = (const float*)d_in[8];
    float* out = (float*)d_out;

    __half *hth, *wqkv, *woh, *qh, *kc, *vc, *ao;
    cudaGetSymbolAddress((void**)&hth,  g_hth);
    cudaGetSymbolAddress((void**)&wqkv, g_wqkv);
    cudaGetSymbolAddress((void**)&woh,  g_woh);
    cudaGetSymbolAddress((void**)&qh,   g_qh);
    cudaGetSymbolAddress((void**)&kc,   g_kc);
    cudaGetSymbolAddress((void**)&vc,   g_vc);
    cudaGetSymbolAddress((void**)&ao,   g_ao);

    // 1. fp16 conversions
    conv_h<<<(SEQ * HID / 8 + 255) / 256, 256>>>((const float4*)hidden, (uint4*)hth, SEQ * HID / 8);
    conv_wcat<<<(HID * 512 + 255) / 256, 256>>>(Wq, wqkv, 2048, 0);
    conv_wcat<<<(HID * 128 + 255) / 256, 256>>>(Wk, wqkv, 512, 2048);
    conv_wcat<<<(HID * 128 + 255) / 256, 256>>>(Wv, wqkv, 512, 2560);
    conv_h<<<(HID * HID / 8 + 255) / 256, 256>>>((const float4*)Wo, (uint4*)woh, HID * HID / 8);

    // 2. fused QKV projection + rope epilogue (writes qh/kc/vc directly)
    cudaFuncSetAttribute(hgemm_qkv, cudaFuncAttributeMaxDynamicSharedMemorySize, SMEM_H);
    hgemm_qkv<<<dim3(NQKV / 128, SEQ / 128), 256, SMEM_H>>>(hth, wqkv, cosb, sinb, qh, kc, vc);

    // 3. retrieval K/V into unified buffers
    conv_ret<<<(NKVH * RLEN * (HDIM / 4) + 255) / 256, 256>>>(rk, kc);
    conv_ret<<<(NKVH * RLEN * (HDIM / 4) + 255) / 256, 256>>>(rv, vc);

    // 4. attention: balanced paired q-tiles, 1 head per CTA
    cudaFuncSetAttribute(attn_tc, cudaFuncAttributeMaxDynamicSharedMemorySize, ATT_SMEM_BYTES);
    attn_tc<<<dim3(16, NHEAD), 128, ATT_SMEM_BYTES>>>(qh, kc, vc, ao);

    // 5. output projection
    cudaFuncSetAttribute(hgemm_out, cudaFuncAttributeMaxDynamicSharedMemorySize, SMEM_H);
    hgemm_out<<<dim3(HID / 128, SEQ / 128), 256, SMEM_H>>>(ao, woh, out);
}

// round 12
// speedup vs baseline: 8.5216x; 1.0821x over previous
#include <cuda_runtime.h>
#include <cuda_fp16.h>
#include <cstdint>

// ---------------- problem constants ----------------
constexpr int SEQ  = 2048;
constexpr int HID  = 2048;
constexpr int NHEAD = 32;
constexpr int NKVH  = 8;
constexpr int HDIM  = 64;
constexpr int RLEN  = 1024;
constexpr int KVTOT = RLEN + SEQ;   // 3072
constexpr int NQKV  = NHEAD * HDIM + 2 * NKVH * HDIM;  // 3072
constexpr float SCALE = 0.125f;
constexpr float LOG2E = 1.44269504088896340736f;

// ---------------- scratch (device globals; no allocs) ----------------
__device__ __half g_hth [SEQ * HID];            // hidden fp16
__device__ __half g_wqkv[HID * NQKV];           // Wq|Wk|Wv fp16 [k][n]
__device__ __half g_woh [HID * HID];            // Wo fp16 [k][n]
__device__ __half g_qh  [SEQ * NHEAD * HDIM];   // roped Q fp16, pre-scaled by SCALE*log2(e)
__device__ __half g_kc  [NKVH * KVTOT * HDIM];  // unified K [hk][tok][d] fp16
__device__ __half g_vc  [NKVH * KVTOT * HDIM];  // unified V [hk][tok][d] fp16
__device__ __half g_ao  [SEQ * NHEAD * HDIM];   // attention out fp16

// ---------------- helpers ----------------
__device__ __forceinline__ unsigned packh2(float x, float y) {
    __half2 h = __floats2half2_rn(x, y);
    return *(unsigned*)&h;
}
__device__ __forceinline__ float ex2(float x) {
    float r;
    asm("ex2.approx.f32 %0, %1;" : "=f"(r) : "f"(x));
    return r;
}
__device__ __forceinline__ unsigned h2ex2(unsigned x) {
    unsigned r;
    asm("ex2.approx.f16x2 %0, %1;" : "=r"(r) : "r"(x));
    return r;
}
__device__ __forceinline__ void mma16(float* c, const unsigned* a, const unsigned* b) {
    asm volatile(
        "mma.sync.aligned.m16n8k16.row.col.f32.f16.f16.f32 "
        "{%0,%1,%2,%3},{%4,%5,%6,%7},{%8,%9},{%0,%1,%2,%3};"
        : "+f"(c[0]), "+f"(c[1]), "+f"(c[2]), "+f"(c[3])
        : "r"(a[0]), "r"(a[1]), "r"(a[2]), "r"(a[3]), "r"(b[0]), "r"(b[1]));
}
__device__ __forceinline__ void ldsm_x4(unsigned* r, unsigned addr) {
    asm volatile("ldmatrix.sync.aligned.m8n8.x4.shared.b16 {%0,%1,%2,%3}, [%4];"
        : "=r"(r[0]), "=r"(r[1]), "=r"(r[2]), "=r"(r[3]) : "r"(addr));
}
__device__ __forceinline__ void ldsm_x4_t(unsigned* r, unsigned addr) {
    asm volatile("ldmatrix.sync.aligned.m8n8.x4.trans.shared.b16 {%0,%1,%2,%3}, [%4];"
        : "=r"(r[0]), "=r"(r[1]), "=r"(r[2]), "=r"(r[3]) : "r"(addr));
}
#define CP16(dst, src) asm volatile("cp.async.cg.shared.global [%0], [%1], 16;" :: "r"(dst), "l"(src))
#define CP_COMMIT()    asm volatile("cp.async.commit_group;")
#define CP_WAIT0()     asm volatile("cp.async.wait_group 0;")
#define CP_WAIT1()     asm volatile("cp.async.wait_group 1;")

// ================= fused conversion kernel (one launch for all prep) =================
// block ranges:
//  [0,2048)      hidden  linear 8/thr
//  [2048,4096)   Wo      linear 8/thr
//  [4096,8192)   Wq      remap  4/thr (ncols 2048 -> wqkv col 0)
//  [8192,9216)   Wk      remap  4/thr (ncols 512  -> wqkv col 2048)
//  [9216,10240)  Wv      remap  4/thr (ncols 512  -> wqkv col 2560)
//  [10240,10496) rk      ret-region 8/thr -> kc
//  [10496,10752) rv      ret-region 8/thr -> vc
constexpr int CONV_BLOCKS = 10752;

__global__ __launch_bounds__(256)
void conv_all(const float* __restrict__ hidden, const float* __restrict__ Wq,
              const float* __restrict__ Wk, const float* __restrict__ Wv,
              const float* __restrict__ Wo, const float* __restrict__ rk,
              const float* __restrict__ rv,
              __half* __restrict__ hth, __half* __restrict__ wqkv,
              __half* __restrict__ woh, __half* __restrict__ kc, __half* __restrict__ vc)
{
    const int b = blockIdx.x, tid = threadIdx.x;
    if (b < 4096) {                        // hidden or Wo, linear
        const float* src = (b < 2048) ? hidden : Wo;
        __half* dst = (b < 2048) ? hth : woh;
        int i = (b & 2047) * 256 + tid;    // 8-elem unit
        float4 a = ((const float4*)src)[2 * i], c = ((const float4*)src)[2 * i + 1];
        ((uint4*)dst)[i] = make_uint4(packh2(a.x, a.y), packh2(a.z, a.w),
                                      packh2(c.x, c.y), packh2(c.z, c.w));
    } else if (b < 8192) {                 // Wq
        int id = (b - 4096) * 256 + tid;
        int k = id >> 9, n4 = (id & 511) * 4;
        float4 v = *(const float4*)&Wq[(size_t)k * 2048 + n4];
        *(uint2*)&wqkv[(size_t)k * NQKV + n4] = make_uint2(packh2(v.x, v.y), packh2(v.z, v.w));
    } else if (b < 10240) {                // Wk / Wv
        const float* src = (b < 9216) ? Wk : Wv;
        const int noff = (b < 9216) ? 2048 : 2560;
        int id = ((b - 8192) & 1023) * 256 + tid;
        int k = id >> 7, n4 = (id & 127) * 4;
        float4 v = *(const float4*)&src[(size_t)k * 512 + n4];
        *(uint2*)&wqkv[(size_t)k * NQKV + noff + n4] = make_uint2(packh2(v.x, v.y), packh2(v.z, v.w));
    } else {                               // rk / rv -> ret region of kc / vc
        const float* src = (b < 10496) ? rk : rv;
        __half* dst = (b < 10496) ? kc : vc;
        int i = ((b - 10240) & 255) * 256 + tid;   // 8-elem unit
        int e = i * 8;
        int hk = e >> 16, rem = e & 65535;         // 1024*64 = 65536 elems per hk
        float4 a = *(const float4*)&src[e];
        float4 c = *(const float4*)&src[e + 4];
        *(uint4*)&dst[(size_t)hk * KVTOT * HDIM + rem] =
            make_uint4(packh2(a.x, a.y), packh2(a.z, a.w),
                       packh2(c.x, c.y), packh2(c.z, c.w));
    }
}

// ================= fp16 GEMM mainloop: 3-stage cp.async, BM=128 BN=128 BK=32 =================
constexpr int GA_STR = 40;             // halfwords
constexpr int GB_STR = 136;
constexpr int GA_HW  = 128 * GA_STR;   // per stage
constexpr int GB_HW  = 32 * GB_STR;
constexpr int SMEM_H = 3 * (GA_HW + GB_HW) * 2;   // 56832 B

__device__ __forceinline__ void hgemm_main(
    const __half* __restrict__ A, const __half* __restrict__ B,
    int K, int N, int bm, int bn, int tid,
    unsigned as_u, unsigned bs_u, float acc[2][8][4])
{
    const int warp = tid >> 5;
    const int lane = tid & 31;
    const int m_base = (warp >> 1) * 32;
    const int n_base = (warp & 1) * 64;

    const int aRow = tid >> 2, aC = (tid & 3) * 8;
    const int bK   = tid >> 4, bN = (tid & 15) * 8;

    const int a_r = lane & 15, a_c = (lane >> 4) << 3;
    const int b_k = ((lane >> 3) & 1) * 8 + (lane & 7), b_n = (lane >> 4) << 3;

    auto issue = [&](int it, int s) {
        const size_t k0 = (size_t)it * 32;
        unsigned ad = as_u + (s * GA_HW + aRow * GA_STR + aC) * 2;
        CP16(ad,                   &A[(size_t)(bm + aRow) * K + k0 + aC]);
        CP16(ad + 64 * GA_STR * 2, &A[(size_t)(bm + aRow + 64) * K + k0 + aC]);
        unsigned bd = bs_u + (s * GB_HW + bK * GB_STR + bN) * 2;
        CP16(bd,                   &B[(k0 + bK) * N + bn + bN]);
        CP16(bd + 16 * GB_STR * 2, &B[(k0 + bK + 16) * N + bn + bN]);
    };

#pragma unroll
    for (int mt = 0; mt < 2; mt++)
#pragma unroll
        for (int nt = 0; nt < 8; nt++)
#pragma unroll
            for (int j = 0; j < 4; j++) acc[mt][nt][j] = 0.f;

    const int niter = K >> 5;
    issue(0, 0); CP_COMMIT();
    issue(1, 1); CP_COMMIT();

    for (int it = 0; it < niter; it++) {
        const int s = it % 3;
        CP_WAIT1();
        __syncthreads();

#pragma unroll
        for (int ks = 0; ks < 2; ks++) {
            const int kb = ks * 16;
            unsigned a[2][4];
#pragma unroll
            for (int mt = 0; mt < 2; mt++)
                ldsm_x4(a[mt], as_u + (s * GA_HW + (m_base + mt * 16 + a_r) * GA_STR + kb + a_c) * 2);
#pragma unroll
            for (int ng = 0; ng < 4; ng++) {
                unsigned b4[4];
                ldsm_x4_t(b4, bs_u + (s * GB_HW + (kb + b_k) * GB_STR + n_base + ng * 16 + b_n) * 2);
                mma16(acc[0][ng * 2],     a[0], b4);
                mma16(acc[0][ng * 2 + 1], a[0], b4 + 2);
                mma16(acc[1][ng * 2],     a[1], b4);
                mma16(acc[1][ng * 2 + 1], a[1], b4 + 2);
            }
        }
        if (it + 2 < niter) issue(it + 2, (it + 2) % 3);
        CP_COMMIT();
    }
}

// ---- fused QKV GEMM: epilogue applies rope + fp16 pack, scatters to qh/kc/vc ----
__global__ __launch_bounds__(256)
void hgemm_qkv(const __half* __restrict__ A, const __half* __restrict__ B,
               const float* __restrict__ cosb, const float* __restrict__ sinb,
               __half* __restrict__ qh, __half* __restrict__ kc, __half* __restrict__ vc)
{
    extern __shared__ __half smh[];
    const unsigned as_u = (unsigned)__cvta_generic_to_shared(smh);
    const unsigned bs_u = as_u + 3 * GA_HW * 2;
    const int tid = threadIdx.x;
    const int bm = blockIdx.y * 128, bn = blockIdx.x * 128;

    float acc[2][8][4];
    hgemm_main(A, B, HID, NQKV, bm, bn, tid, as_u, bs_u, acc);

    const int warp = tid >> 5, lane = tid & 31;
    const int gid = lane >> 2, tig = lane & 3;
    const int m_base = (warp >> 1) * 32;
    const int n_warp0 = bn + (warp & 1) * 64;   // 64-aligned: one head, one region

    if (n_warp0 < 2560) {
        // q or k: rope pairs (i, i+32) are (nt, nt+4) in-thread
        // q additionally pre-scaled by SCALE*log2(e) for the exp2 softmax
        const float sc = (n_warp0 < 2048) ? SCALE * LOG2E : 1.f;
#pragma unroll
        for (int mt = 0; mt < 2; mt++) {
#pragma unroll
            for (int half = 0; half < 2; half++) {
                const int row = bm + m_base + mt * 16 + gid + half * 8;   // token
                const int jo = half * 2;
#pragma unroll
                for (int nt = 0; nt < 4; nt++) {
                    const int i = nt * 8 + 2 * tig;
                    float2 cc = *(const float2*)&cosb[(size_t)row * 64 + i];
                    float2 ss = *(const float2*)&sinb[(size_t)row * 64 + i];
                    float x00 = acc[mt][nt][jo],     x01 = acc[mt][nt][jo + 1];
                    float x10 = acc[mt][nt + 4][jo], x11 = acc[mt][nt + 4][jo + 1];
                    unsigned lo = packh2((x00 * cc.x - x10 * ss.x) * sc,
                                         (x01 * cc.y - x11 * ss.y) * sc);
                    unsigned hi = packh2((x10 * cc.x + x00 * ss.x) * sc,
                                         (x11 * cc.y + x01 * ss.y) * sc);
                    __half* d0;
                    if (n_warp0 < 2048) {
                        d0 = qh + (size_t)row * 2048 + n_warp0 + i;
                    } else {
                        const int rel = n_warp0 - 2048 + i;
                        d0 = kc + ((size_t)(rel >> 6) * KVTOT + RLEN + row) * HDIM + (rel & 63);
                    }
                    *(unsigned*)d0        = lo;
                    *(unsigned*)(d0 + 32) = hi;
                }
            }
        }
    } else {
        // v region: fp16 store straight into unified vc[hk][RLEN+tok][d]
#pragma unroll
        for (int mt = 0; mt < 2; mt++) {
#pragma unroll
            for (int half = 0; half < 2; half++) {
                const int row = bm + m_base + mt * 16 + gid + half * 8;
                const int jo = half * 2;
#pragma unroll
                for (int nt = 0; nt < 8; nt++) {
                    const int rel = n_warp0 + nt * 8 + 2 * tig - 2560;
                    __half* d0 = vc + ((size_t)(rel >> 6) * KVTOT + RLEN + row) * HDIM + (rel & 63);
                    *(unsigned*)d0 = packh2(acc[mt][nt][jo], acc[mt][nt][jo + 1]);
                }
            }
        }
    }
}

// ---- Wo GEMM: fp32 out ----
__global__ __launch_bounds__(256)
void hgemm_out(const __half* __restrict__ A, const __half* __restrict__ B,
               float* __restrict__ C)
{
    extern __shared__ __half smh[];
    const unsigned as_u = (unsigned)__cvta_generic_to_shared(smh);
    const unsigned bs_u = as_u + 3 * GA_HW * 2;
    const int tid = threadIdx.x;
    const int bm = blockIdx.y * 128, bn = blockIdx.x * 128;

    float acc[2][8][4];
    hgemm_main(A, B, HID, HID, bm, bn, tid, as_u, bs_u, acc);

    const int warp = tid >> 5, lane = tid & 31;
    const int gid = lane >> 2, tig = lane & 3;
    const int m_base = (warp >> 1) * 32;
    const int n_base = (warp & 1) * 64;
#pragma unroll
    for (int mt = 0; mt < 2; mt++)
#pragma unroll
        for (int nt = 0; nt < 8; nt++) {
            int row = bm + m_base + mt * 16 + gid;
            int col = bn + n_base + nt * 8 + 2 * tig;
            *(float2*)&C[(size_t)row * HID + col]       = make_float2(acc[mt][nt][0], acc[mt][nt][1]);
            *(float2*)&C[(size_t)(row + 8) * HID + col] = make_float2(acc[mt][nt][2], acc[mt][nt][3]);
        }
}

// ================= fp16 flash attention: balanced paired q-tiles =================
// 128 thr = 4 warps, 1 head per CTA, forced 4 CTAs/SM. CTA bx does q-tiles
// {16+bx, 15-bx} -> constant 35 tile-iters. Softmax: f16x2 ex2 + MMA row-sum.
constexpr int AT_STR = 72;
constexpr int AT_HW  = 64 * AT_STR;
constexpr int ATT_SMEM_BYTES = (AT_HW * 5) * 2;  // 46080 B

__global__ __launch_bounds__(128, 4)
void attn_tc(const __half* __restrict__ qh, const __half* __restrict__ kc,
             const __half* __restrict__ vc, __half* __restrict__ out)
{
    extern __shared__ __half sm[];
    const unsigned sm_u = (unsigned)__cvta_generic_to_shared(sm);

    const int bx   = blockIdx.x;           // 0..15 pair index
    const int h    = blockIdx.y;
    const int hk   = h >> 2;
    const int tid  = threadIdx.x;
    const int warp = tid >> 5;
    const int lane = tid & 31;
    const int gid  = lane >> 2;
    const int tig  = lane & 3;
    const int q0   = warp * 16;

    // fragment lane addressing
    const int a_r = lane & 15, a_c = (lane >> 4) << 3;                              // A frag
    const int b_r = ((lane >> 4) << 3) + (lane & 7), b_c = ((lane >> 3) & 1) * 8;   // B frag (K)
    const int v_k = ((lane >> 3) & 1) * 8 + (lane & 7), v_n = (lane >> 4) << 3;     // B frag (V, trans)

    const __half* kbase = kc + (size_t)hk * KVTOT * HDIM;
    const __half* vbase = vc + (size_t)hk * KVTOT * HDIM;

    const unsigned ONE2 = 0x3C003C00u;     // half2(1, 1)
    const unsigned ones2[2] = {ONE2, ONE2};

    for (int phase = 0; phase < 2; phase++) {
        const int t = phase ? (15 - bx) : (16 + bx);

        const int hasret = (t >= 1) ? 1 : 0;
        const int ntiles = (t + 1) + hasret;
        const int rb = ((t < 16) ? t : 16) - 1;

        auto tokbase_of = [&](int it) {
            return (hasret && it == 0) ? rb * 64 : RLEN + (it - hasret) * 64;
        };
        auto issue_kv = [&](int it, int s) {
            const int tb2 = tokbase_of(it);
            const unsigned koff = sm_u + (1 + 2 * s) * AT_HW * 2;
            const unsigned voff = koff + AT_HW * 2;
#pragma unroll
            for (int j = 0; j < 4; j++) {
                int id = tid + j * 128;
                int r = id >> 3, c8 = (id & 7) * 8;
                CP16(koff + (r * AT_STR + c8) * 2, &kbase[(size_t)(tb2 + r) * HDIM + c8]);
                CP16(voff + (r * AT_STR + c8) * 2, &vbase[(size_t)(tb2 + r) * HDIM + c8]);
            }
        };

        // prologue: Q + KV(0)
#pragma unroll
        for (int j = 0; j < 4; j++) {
            int id = tid + j * 128;
            int r = id >> 3, c8 = (id & 7) * 8;
            CP16(sm_u + (r * AT_STR + c8) * 2,
                 &qh[(size_t)(t * 64 + r) * (NHEAD * HDIM) + h * HDIM + c8]);
        }
        issue_kv(0, 0);
        CP_COMMIT();

        unsigned qa[4][4];
        float m_lo = -1e30f, m_hi = -1e30f, l_lo = 0.f, l_hi = 0.f;
        float O[8][4];
#pragma unroll
        for (int nt = 0; nt < 8; nt++)
#pragma unroll
            for (int j = 0; j < 4; j++) O[nt][j] = 0.f;

        for (int it = 0; it < ntiles; it++) {
            const int s = it & 1;
            const bool isret = hasret && (it == 0);
            const int jt = it - hasret;

            if (it + 1 < ntiles) { issue_kv(it + 1, s ^ 1); CP_COMMIT(); CP_WAIT1(); }
            else                 { CP_WAIT0(); }
            __syncthreads();

            if (it == 0) {
#pragma unroll
                for (int kt = 0; kt < 4; kt++)
                    ldsm_x4(qa[kt], sm_u + ((q0 + a_r) * AT_STR + kt * 16 + a_c) * 2);
            }

            const unsigned koff = sm_u + (1 + 2 * s) * AT_HW * 2;
            const unsigned voff = koff + AT_HW * 2;

            // S = Q K^T  (log2-domain logits: Q pre-scaled by SCALE*log2e)
            float sacc[8][4];
#pragma unroll
            for (int nt = 0; nt < 8; nt++)
#pragma unroll
                for (int j = 0; j < 4; j++) sacc[nt][j] = 0.f;

#pragma unroll
            for (int kt = 0; kt < 4; kt++) {
                const int kb = kt * 16;
#pragma unroll
                for (int ng = 0; ng < 4; ng++) {
                    unsigned b4[4];
                    ldsm_x4(b4, koff + ((ng * 16 + b_r) * AT_STR + kb + b_c) * 2);
                    mma16(sacc[ng * 2],     qa[kt], b4);
                    mma16(sacc[ng * 2 + 1], qa[kt], b4 + 2);
                }
            }

            // mask (new-token tiles only; retrieval block fully valid)
            if (!isret) {
                const int s_lo = t * 64 + q0 + gid;
                const int s_hi = s_lo + 8;
#pragma unroll
                for (int nt = 0; nt < 8; nt++) {
#pragma unroll
                    for (int j = 0; j < 2; j++) {
                        int n = jt * 64 + nt * 8 + 2 * tig + j;
                        bool inval = (n < 1);
                        if (inval || n > s_lo) sacc[nt][j]     = -1e30f;
                        if (inval || n > s_hi) sacc[nt][j + 2] = -1e30f;
                    }
                }
            }

            // online softmax (base-2): row max via shuffles
            float lm_lo = -1e30f, lm_hi = -1e30f;
#pragma unroll
            for (int nt = 0; nt < 8; nt++) {
                lm_lo = fmaxf(lm_lo, fmaxf(sacc[nt][0], sacc[nt][1]));
                lm_hi = fmaxf(lm_hi, fmaxf(sacc[nt][2], sacc[nt][3]));
            }
            lm_lo = fmaxf(lm_lo, __shfl_xor_sync(0xffffffffu, lm_lo, 1));
            lm_lo = fmaxf(lm_lo, __shfl_xor_sync(0xffffffffu, lm_lo, 2));
            lm_hi = fmaxf(lm_hi, __shfl_xor_sync(0xffffffffu, lm_hi, 1));
            lm_hi = fmaxf(lm_hi, __shfl_xor_sync(0xffffffffu, lm_hi, 2));
            const float mn_lo = fmaxf(m_lo, lm_lo);
            const float mn_hi = fmaxf(m_hi, lm_hi);

            // P = 2^(S - mn) in fp16 pairs (f16x2 MUFU), pre-packed for PV mma
            unsigned plo[8], phi[8];
#pragma unroll
            for (int nt = 0; nt < 8; nt++) {
                plo[nt] = h2ex2(packh2(sacc[nt][0] - mn_lo, sacc[nt][1] - mn_lo));
                phi[nt] = h2ex2(packh2(sacc[nt][2] - mn_hi, sacc[nt][3] - mn_hi));
            }

            const float f_lo = ex2(m_lo - mn_lo);
            const float f_hi = ex2(m_hi - mn_hi);
            m_lo = mn_lo; m_hi = mn_hi;
#pragma unroll
            for (int nt = 0; nt < 8; nt++) {
                O[nt][0] *= f_lo; O[nt][1] *= f_lo;
                O[nt][2] *= f_hi; O[nt][3] *= f_hi;
            }

            // row-sum via MMA against ones + O += P @ V
            float lacc[4] = {0.f, 0.f, 0.f, 0.f};
#pragma unroll
            for (int kt = 0; kt < 4; kt++) {
                unsigned pa[4] = {plo[2 * kt], phi[2 * kt], plo[2 * kt + 1], phi[2 * kt + 1]};
                mma16(lacc, pa, ones2);
#pragma unroll
                for (int ng = 0; ng < 4; ng++) {
                    unsigned b4[4];
                    ldsm_x4_t(b4, voff + ((kt * 16 + v_k) * AT_STR + ng * 16 + v_n) * 2);
                    mma16(O[ng * 2],     pa, b4);
                    mma16(O[ng * 2 + 1], pa, b4 + 2);
                }
            }
            l_lo = l_lo * f_lo + lacc[0];
            l_hi = l_hi * f_hi + lacc[2];
            __syncthreads();   // stage reuse guard
        }

        // epilogue for this q-tile
        const float inv_lo = (m_lo > -1e29f) ? (1.f / l_lo) : 0.f;
        const float inv_hi = (m_hi > -1e29f) ? (1.f / l_hi) : 0.f;
#pragma unroll
        for (int nt = 0; nt < 8; nt++) {
            int col = nt * 8 + 2 * tig;
            size_t r_lo = (size_t)(t * 64 + q0 + gid)     * (NHEAD * HDIM) + h * HDIM + col;
            size_t r_hi = (size_t)(t * 64 + q0 + gid + 8) * (NHEAD * HDIM) + h * HDIM + col;
            *(unsigned*)&out[r_lo] = packh2(O[nt][0] * inv_lo, O[nt][1] * inv_lo);
            *(unsigned*)&out[r_hi] = packh2(O[nt][2] * inv_hi, O[nt][3] * inv_hi);
        }
    }
}

// ---------------- launch ----------------
extern "C" void kernel_launch(void* const* d_in, const int* in_sizes, int n_in,
                              void* d_out, int out_size)
{
    const float* hidden = (const float*)d_in[0];
    const float* cosb   = (const float*)d_in[1];
    const float* sinb   = (const float*)d_in[2];
    const float* rk     = (const float*)d_in[3];
    const float* rv     = (const float*)d_in[4];
    const float* Wq     = (const float*)d_in[5];
    const float* Wk     = (const float*)d_in[6];
    const float* Wv     = (const float*)d_in[7];
    const float* Wo     = (const float*)d_in[8];
    float* out = (float*)d_out;

    __half *hth, *wqkv, *woh, *qh, *kc, *vc, *ao;
    cudaGetSymbolAddress((void**)&hth,  g_hth);
    cudaGetSymbolAddress((void**)&wqkv, g_wqkv);
    cudaGetSymbolAddress((void**)&woh,  g_woh);
    cudaGetSymbolAddress((void**)&qh,   g_qh);
    cudaGetSymbolAddress((void**)&kc,   g_kc);
    cudaGetSymbolAddress((void**)&vc,   g_vc);
    cudaGetSymbolAddress((void**)&ao,   g_ao);

    // 1. all fp16 conversions in one launch
    conv_all<<<CONV_BLOCKS, 256>>>(hidden, Wq, Wk, Wv, Wo, rk, rv,
                                   hth, wqkv, woh, kc, vc);

    // 2. fused QKV projection + rope epilogue (writes qh/kc/vc directly)
    cudaFuncSetAttribute(hgemm_qkv, cudaFuncAttributeMaxDynamicSharedMemorySize, SMEM_H);
    hgemm_qkv<<<dim3(NQKV / 128, SEQ / 128), 256, SMEM_H>>>(hth, wqkv, cosb, sinb, qh, kc, vc);

    // 3. attention: balanced paired q-tiles, 1 head per CTA, 4 CTAs/SM
    cudaFuncSetAttribute(attn_tc, cudaFuncAttributeMaxDynamicSharedMemorySize, ATT_SMEM_BYTES);
    attn_tc<<<dim3(16, NHEAD), 128, ATT_SMEM_BYTES>>>(qh, kc, vc, ao);

    // 4. output projection
    cudaFuncSetAttribute(hgemm_out, cudaFuncAttributeMaxDynamicSharedMemorySize, SMEM_H);
    hgemm_out<<<dim3(HID / 128, SEQ / 128), 256, SMEM_H>>>(ao, woh, out);
}